// round 14
// baseline (speedup 1.0000x reference)
#include <cuda_runtime.h>
#include <cuda_bf16.h>
#include <cuda_fp16.h>
#include <cstdint>

// Problem constants
#define B_  4
#define N_  2048
#define C_  768
#define H_  12
#define HD_ 64
#define NC3 2304
// q pre-scale folded with log2(e) so attention can use raw ex2
#define QSCALE_ (0.125f * 1.44269504088896340736f)

#define QKV_SZ ((size_t)B_ * H_ * N_ * HD_)   // 6291456

// Static scratch — all tensor-core operands fp16.
// A-operands: hi/lo pairs (near-exact); B-operands (weights/K): single fp16.
__device__ __half g_qhi[QKV_SZ], g_qlo[QKV_SZ];          // [B,H,N,HD], pre-scaled
__device__ __half g_khi[QKV_SZ];                          // [B,H,N,HD]
__device__ __half g_vhi[QKV_SZ], g_vlo[QKV_SZ];          // [B,H,HD,N] (transposed)
__device__ __half g_xhi[(size_t)B_ * N_ * C_], g_xlo[(size_t)B_ * N_ * C_];
__device__ __half g_w1h[(size_t)C_ * NC3];
__device__ __half g_w2h[(size_t)C_ * C_];
__device__ __half g_aohi[(size_t)B_ * N_ * C_], g_aolo[(size_t)B_ * N_ * C_];

// ---------------------------------------------------------------------------
// Helpers
// ---------------------------------------------------------------------------
__device__ __forceinline__ uint32_t smem_u32(const void* p) {
    uint32_t a;
    asm("{ .reg .u64 t; cvta.to.shared.u64 t, %1; cvt.u32.u64 %0, t; }"
        : "=r"(a) : "l"(p));
    return a;
}
__device__ __forceinline__ void ldmx4(uint32_t* r, uint32_t addr) {
    asm volatile("ldmatrix.sync.aligned.m8n8.x4.shared.b16 {%0,%1,%2,%3}, [%4];"
                 : "=r"(r[0]), "=r"(r[1]), "=r"(r[2]), "=r"(r[3]) : "r"(addr));
}
__device__ __forceinline__ void ldmx4t(uint32_t* r, uint32_t addr) {
    asm volatile("ldmatrix.sync.aligned.m8n8.x4.trans.shared.b16 {%0,%1,%2,%3}, [%4];"
                 : "=r"(r[0]), "=r"(r[1]), "=r"(r[2]), "=r"(r[3]) : "r"(addr));
}
__device__ __forceinline__ void mma16816h(float* c, const uint32_t* a,
                                          const uint32_t* b) {
    asm volatile(
        "mma.sync.aligned.m16n8k16.row.col.f32.f16.f16.f32 "
        "{%0,%1,%2,%3}, {%4,%5,%6,%7}, {%8,%9}, {%0,%1,%2,%3};"
        : "+f"(c[0]), "+f"(c[1]), "+f"(c[2]), "+f"(c[3])
        : "r"(a[0]), "r"(a[1]), "r"(a[2]), "r"(a[3]), "r"(b[0]), "r"(b[1]));
}
__device__ __forceinline__ void split2h(float x, float y, uint32_t& hi, uint32_t& lo) {
    __half2 h = __floats2half2_rn(x, y);
    float hx = __half2float(__low2half(h)), hy = __half2float(__high2half(h));
    __half2 l = __floats2half2_rn(x - hx, y - hy);
    hi = *(uint32_t*)&h;
    lo = *(uint32_t*)&l;
}
__device__ __forceinline__ uint32_t pack_h2(float x, float y) {
    __half2 h = __floats2half2_rn(x, y);
    return *(uint32_t*)&h;
}
__device__ __forceinline__ float ex2(float x) {
    float y;
    asm("ex2.approx.ftz.f32 %0, %1;" : "=f"(y) : "f"(x));
    return y;
}
__device__ __forceinline__ void cpa16(uint32_t dst, const void* src) {
    asm volatile("cp.async.cg.shared.global [%0], [%1], 16;" :: "r"(dst), "l"(src));
}
#define CP_COMMIT()  asm volatile("cp.async.commit_group;")
#define CP_WAIT(n)   asm volatile("cp.async.wait_group " #n ";")

// ---------------------------------------------------------------------------
// Kernel 0: fp32 -> fp16 conversions. x: hi+lo split; weights: single round.
// ---------------------------------------------------------------------------
#define NX4  ((B_ * N_ * C_) / 4)
#define NW14 ((C_ * NC3) / 4)
#define NW24 ((C_ * C_) / 4)

__global__ __launch_bounds__(256) void conv_all(
    const float* __restrict__ x, const float* __restrict__ w1,
    const float* __restrict__ w2)
{
    int i = blockIdx.x * 256 + threadIdx.x;
    if (i < NX4) {
        float4 v = ((const float4*)x)[i];
        uint32_t h0, l0, h1, l1;
        split2h(v.x, v.y, h0, l0);
        split2h(v.z, v.w, h1, l1);
        ((uint2*)g_xhi)[i] = make_uint2(h0, h1);
        ((uint2*)g_xlo)[i] = make_uint2(l0, l1);
    } else if (i < NX4 + NW14) {
        int j = i - NX4;
        float4 v = ((const float4*)w1)[j];
        ((uint2*)g_w1h)[j] = make_uint2(pack_h2(v.x, v.y), pack_h2(v.z, v.w));
    } else if (i < NX4 + NW14 + NW24) {
        int j = i - NX4 - NW14;
        float4 v = ((const float4*)w2)[j];
        ((uint2*)g_w2h)[j] = make_uint2(pack_h2(v.x, v.y), pack_h2(v.z, v.w));
    }
}

// ---------------------------------------------------------------------------
// GEMM: fp16 asymmetric 2-term HMMA (round-12 proven structure: 3-stage ring,
// two syncs per stage). 128x128 CTA tile, 8 warps, K-stage 32, 2 CTAs/SM.
// Stage layout (bytes): Ahi[0,8K) Alo[8K,16K) Bh[16K,24K)
// ---------------------------------------------------------------------------
#define STG_G  24576
#define NSTG   24

__device__ __forceinline__ uint32_t swzA(int r, int c) {
    return (uint32_t)(r * 64 + ((c ^ ((r >> 1) & 3)) << 4));
}
__device__ __forceinline__ uint32_t swzB(int r, int c) {
    return (uint32_t)(r * 256 + ((c ^ (r & 7)) << 4));
}

template <int LDB>
__device__ __forceinline__ void gemm_load_stage(
    const __half* __restrict__ Ahi, const __half* __restrict__ Alo,
    const __half* __restrict__ Bh,
    int m0, int n0, int s, uint32_t sbase, int tid)
{
    const int k0 = s * 32;
    #pragma unroll
    for (int j = 0; j < 2; j++) {
        int idx = tid + 256 * j;
        int row = idx >> 2, c = idx & 3;
        size_t gi = (size_t)(m0 + row) * C_ + k0 + c * 8;
        uint32_t d = sbase + swzA(row, c);
        cpa16(d, Ahi + gi);
        cpa16(d + 8192, Alo + gi);
    }
    #pragma unroll
    for (int j = 0; j < 2; j++) {
        int idx = tid + 256 * j;
        int row = idx >> 4, c = idx & 15;
        size_t gi = (size_t)(k0 + row) * LDB + n0 + c * 8;
        cpa16(sbase + 16384 + swzB(row, c), Bh + gi);
    }
}

template <int MODE>
__global__ __launch_bounds__(256, 2) void tc_gemm(
    const __half* __restrict__ Ahi, const __half* __restrict__ Alo,
    const __half* __restrict__ Bh,
    const float* __restrict__ biasRow,
    const float* __restrict__ qb, const float* __restrict__ kb,
    const float* __restrict__ vb, float* __restrict__ outp)
{
    constexpr int LDB = (MODE == 0) ? NC3 : C_;
    extern __shared__ __align__(16) char smem[];
    const uint32_t sb = smem_u32(smem);
    const int tid = threadIdx.x, lid = tid & 31, wid = tid >> 5;
    const int wm = wid >> 2, wn = wid & 3;
    const int n0 = blockIdx.x * 128, m0 = blockIdx.y * 128;

    float c[4][4][4];
    #pragma unroll
    for (int i = 0; i < 4; i++)
        #pragma unroll
        for (int j = 0; j < 4; j++)
            #pragma unroll
            for (int k = 0; k < 4; k++) c[i][j][k] = 0.f;

    #pragma unroll
    for (int s = 0; s < 3; s++) {
        gemm_load_stage<LDB>(Ahi, Alo, Bh, m0, n0, s, sb + s * STG_G, tid);
        CP_COMMIT();
    }

    const int arow = wm * 64 + (lid & 15);
    const int ac   = lid >> 4;
    const int bkr  = lid & 15;
    const int bch  = lid >> 4;

#define GEMM_COMPUTE(SIDX)                                                     \
    do {                                                                       \
        const uint32_t base = sb + ((SIDX) % 3) * STG_G;                       \
        _Pragma("unroll")                                                      \
        for (int kk = 0; kk < 2; kk++) {                                       \
            uint32_t ah[4][4], al[4][4];                                       \
            _Pragma("unroll")                                                  \
            for (int mt = 0; mt < 4; mt++) {                                   \
                int r = arow + mt * 16;                                        \
                uint32_t ad = base + swzA(r, kk * 2 + ac);                     \
                ldmx4(ah[mt], ad);                                             \
                ldmx4(al[mt], ad + 8192);                                      \
            }                                                                  \
            uint32_t bh[2][4];                                                 \
            _Pragma("unroll")                                                  \
            for (int np = 0; np < 2; np++) {                                   \
                uint32_t ad = base + 16384                                     \
                    + swzB(kk * 16 + bkr, wn * 4 + np * 2 + bch);              \
                ldmx4t(bh[np], ad);                                            \
            }                                                                  \
            _Pragma("unroll")                                                  \
            for (int mt = 0; mt < 4; mt++)                                     \
                _Pragma("unroll")                                              \
                for (int nt = 0; nt < 4; nt++)                                 \
                    mma16816h(c[mt][nt], ah[mt], &bh[nt >> 1][(nt & 1) * 2]);  \
            _Pragma("unroll")                                                  \
            for (int mt = 0; mt < 4; mt++)                                     \
                _Pragma("unroll")                                              \
                for (int nt = 0; nt < 4; nt++)                                 \
                    mma16816h(c[mt][nt], al[mt], &bh[nt >> 1][(nt & 1) * 2]);  \
        }                                                                      \
    } while (0)

    for (int s = 0; s < NSTG - 3; s++) {
        CP_WAIT(2);
        __syncthreads();
        GEMM_COMPUTE(s);
        __syncthreads();
        gemm_load_stage<LDB>(Ahi, Alo, Bh, m0, n0, s + 3,
                             sb + ((s + 3) % 3) * STG_G, tid);
        CP_COMMIT();
    }
    CP_WAIT(2); __syncthreads(); GEMM_COMPUTE(NSTG - 3); __syncthreads();
    CP_WAIT(1); __syncthreads(); GEMM_COMPUTE(NSTG - 2); __syncthreads();
    CP_WAIT(0); __syncthreads(); GEMM_COMPUTE(NSTG - 1);

    // Epilogue (direct from fragments)
    const int g = lid >> 2, t4 = lid & 3;
    if (MODE == 0) {
        const int s3 = n0 / C_;
        const int loc0 = n0 - s3 * C_;
        #pragma unroll
        for (int mt = 0; mt < 4; mt++) {
            #pragma unroll
            for (int nt = 0; nt < 4; nt++) {
                const int colT = wn * 32 + nt * 8 + 2 * t4;
                const int loc = loc0 + colT;
                const int hh = loc >> 6, dd = loc & 63;
                const float b0v = biasRow[n0 + colT];
                const float b1v = biasRow[n0 + colT + 1];
                #pragma unroll
                for (int hf = 0; hf < 2; hf++) {
                    const int m = m0 + wm * 64 + mt * 16 + g + hf * 8;
                    const int bb = m >> 11, nn = m & 2047;
                    const size_t bidx =
                        (((size_t)bb * H_ + hh) * N_ + nn) * HD_ + dd;
                    float v0 = c[mt][nt][2 * hf] + b0v;
                    float v1 = c[mt][nt][2 * hf + 1] + b1v;
                    if (s3 == 0) {
                        v0 = (v0 + qb[bidx]) * QSCALE_;
                        v1 = (v1 + qb[bidx + 1]) * QSCALE_;
                        uint32_t hi, lo;
                        split2h(v0, v1, hi, lo);
                        *(uint32_t*)&g_qhi[bidx] = hi;
                        *(uint32_t*)&g_qlo[bidx] = lo;
                    } else if (s3 == 1) {
                        v0 += kb[bidx];
                        v1 += kb[bidx + 1];
                        *(uint32_t*)&g_khi[bidx] = pack_h2(v0, v1);
                    } else {
                        v0 += vb[bidx];
                        v1 += vb[bidx + 1];
                        const size_t vix =
                            (((size_t)bb * H_ + hh) * HD_ + dd) * N_ + nn;
                        __half h0 = __float2half_rn(v0);
                        __half h1 = __float2half_rn(v1);
                        g_vhi[vix] = h0;
                        g_vlo[vix] = __float2half_rn(v0 - __half2float(h0));
                        g_vhi[vix + N_] = h1;
                        g_vlo[vix + N_] = __float2half_rn(v1 - __half2float(h1));
                    }
                }
            }
        }
    } else {
        #pragma unroll
        for (int mt = 0; mt < 4; mt++)
            #pragma unroll
            for (int nt = 0; nt < 4; nt++) {
                const int colT = wn * 32 + nt * 8 + 2 * t4;
                const float b0v = biasRow[n0 + colT];
                const float b1v = biasRow[n0 + colT + 1];
                #pragma unroll
                for (int hf = 0; hf < 2; hf++) {
                    const int m = m0 + wm * 64 + mt * 16 + g + hf * 8;
                    float2 r;
                    r.x = c[mt][nt][2 * hf] + b0v;
                    r.y = c[mt][nt][2 * hf + 1] + b1v;
                    *(float2*)&outp[(size_t)m * C_ + n0 + colT] = r;
                }
            }
    }
}

// ---------------------------------------------------------------------------
// Attention: fp16 HMMA flash attention with DEFERRED PV.
// 128 q-rows/CTA, 8 warps x 16 rows, 64-key chunks, XOR-swizzled smem,
// 4-stage cp.async ring (96KB), 2 CTAs/SM, two syncs per chunk.
// Per chunk s: QK(s) -> max-reduce(s) -> [PV(s-1) MMAs interleaved with
// ex2(s) on MUFU] -> O*=corr(s). PV(s-1) is independent of softmax(s), so
// the tensor pipe stays busy during the MUFU block.
// Stage layout (bytes): Kh[0,8K) Vh[8K,16K) Vl[16K,24K)
// ---------------------------------------------------------------------------
#define STG_A   24576
#define NCHUNK  32
#define SMEM_AT (4 * STG_A)   // 98304

__device__ __forceinline__ uint32_t swzK(int r, int c) {
    return (uint32_t)(r * 128 + ((c ^ (r & 7)) << 4));
}

__device__ __forceinline__ void attn_load(
    size_t hoff, size_t voff, int kt, uint32_t sbase, int tid)
{
    #pragma unroll
    for (int j = 0; j < 2; j++) {
        int idx = 2 * tid + j;            // 0..511
        int row = idx >> 3, ch = idx & 7;
        uint32_t d = sbase + swzK(row, ch);
        size_t ki = hoff + (size_t)(kt + row) * HD_ + ch * 8;
        cpa16(d, g_khi + ki);
        size_t vi = voff + (size_t)row * N_ + kt + ch * 8;
        cpa16(d + 8192,  g_vhi + vi);
        cpa16(d + 16384, g_vlo + vi);
    }
}

__global__ __launch_bounds__(256, 2) void attn_kernel()
{
    extern __shared__ __align__(16) char smem[];
    const uint32_t sb = smem_u32(smem);
    const int tid = threadIdx.x, lid = tid & 31, wq = tid >> 5;
    const int qt = blockIdx.x, h = blockIdx.y, b = blockIdx.z;
    const size_t hoff = (size_t)(b * H_ + h) * N_ * HD_;
    const size_t voff = (size_t)(b * H_ + h) * HD_ * N_;
    const int q0 = qt * 128;

    // ---- stage Q (hi at [0,16K) in 2x8K halves, lo at +32K), then frags
    #pragma unroll
    for (int j = 0; j < 4; j++) {
        int cid = tid + 256 * j;          // 0..1023
        int row = cid >> 3, ch = cid & 7;
        size_t ga = hoff + (size_t)(q0 + row) * HD_ + ch * 8;
        uint32_t d = swzK(row & 63, ch) + ((row >> 6) << 13);
        *(float4*)(smem + d) = *(const float4*)&g_qhi[ga];
        *(float4*)(smem + d + 32768) = *(const float4*)&g_qlo[ga];
    }
    __syncthreads();
    uint32_t aqh[4][4], aql[4][4];
    {
        int row = wq * 16 + (lid & 15);
        int ch0 = (lid >> 4);
        #pragma unroll
        for (int kk = 0; kk < 4; kk++) {
            uint32_t ad = sb + ((row >> 6) << 13) + swzK(row & 63, kk * 2 + ch0);
            ldmx4(aqh[kk], ad);
            ldmx4(aql[kk], ad + 32768);
        }
    }
    __syncthreads();

    // ---- prologue: K/V chunks 0,1
    attn_load(hoff, voff, 0, sb, tid);
    CP_COMMIT();
    attn_load(hoff, voff, 64, sb + STG_A, tid);
    CP_COMMIT();

    float O[8][4];
    #pragma unroll
    for (int i = 0; i < 8; i++)
        #pragma unroll
        for (int j = 0; j < 4; j++) O[i][j] = 0.f;
    float m0r = -1e30f, m1r = -1e30f, l0 = 0.f, l1 = 0.f;
    uint32_t ph[16];                      // held P(s-1), packed fp16x2
    #pragma unroll
    for (int i = 0; i < 16; i++) ph[i] = 0;

    const int grp = lid >> 3, l8 = lid & 7;
    const int rAdd = ((grp >> 1) << 3) + l8;
    const int cAdd3 = (grp & 1);

#define ATTN_COMPUTE(SIDX, DOPV)                                               \
    do {                                                                       \
        const uint32_t bqk = sb + ((SIDX) & 3) * STG_A;                        \
        const uint32_t bpv = sb + (((SIDX) + 3) & 3) * STG_A;                  \
        float S[8][4];                                                         \
        _Pragma("unroll")                                                      \
        for (int i = 0; i < 8; i++)                                            \
            _Pragma("unroll")                                                  \
            for (int j = 0; j < 4; j++) S[i][j] = 0.f;                         \
        _Pragma("unroll")                                                      \
        for (int kk = 0; kk < 4; kk++) {                                       \
            _Pragma("unroll")                                                  \
            for (int ng = 0; ng < 4; ng++) {                                   \
                uint32_t kh[4];                                                \
                uint32_t ad = bqk + swzK(ng * 16 + rAdd, kk * 2 + cAdd3);      \
                ldmx4(kh, ad);                                                 \
                mma16816h(S[2 * ng],     aqh[kk], kh);                         \
                mma16816h(S[2 * ng],     aql[kk], kh);                         \
                mma16816h(S[2 * ng + 1], aqh[kk], kh + 2);                     \
                mma16816h(S[2 * ng + 1], aql[kk], kh + 2);                     \
            }                                                                  \
        }                                                                      \
        float mx0 = S[0][0], mx1 = S[0][2];                                    \
        _Pragma("unroll")                                                      \
        for (int nt = 0; nt < 8; nt++) {                                       \
            mx0 = fmaxf(mx0, fmaxf(S[nt][0], S[nt][1]));                       \
            mx1 = fmaxf(mx1, fmaxf(S[nt][2], S[nt][3]));                       \
        }                                                                      \
        mx0 = fmaxf(mx0, __shfl_xor_sync(0xffffffffu, mx0, 1));                \
        mx0 = fmaxf(mx0, __shfl_xor_sync(0xffffffffu, mx0, 2));                \
        mx1 = fmaxf(mx1, __shfl_xor_sync(0xffffffffu, mx1, 1));                \
        mx1 = fmaxf(mx1, __shfl_xor_sync(0xffffffffu, mx1, 2));                \
        const float mn0 = fmaxf(m0r, mx0), mn1 = fmaxf(m1r, mx1);              \
        const float cr0 = ex2(m0r - mn0), cr1 = ex2(m1r - mn1);                \
        float ls0 = 0.f, ls1 = 0.f;                                            \
        uint32_t pn[16];                                                       \
        _Pragma("unroll")                                                      \
        for (int kc = 0; kc < 4; kc++) {                                       \
            if (DOPV) {                                                        \
                _Pragma("unroll")                                              \
                for (int ng = 0; ng < 4; ng++) {                               \
                    uint32_t vh[4], vl[4];                                     \
                    uint32_t ad = bpv + 8192                                   \
                        + swzK(ng * 16 + rAdd, kc * 2 + cAdd3);                \
                    ldmx4(vh, ad);                                             \
                    ldmx4(vl, ad + 8192);                                      \
                    mma16816h(O[2 * ng],     ph + 4 * kc, vh);                 \
                    mma16816h(O[2 * ng],     ph + 4 * kc, vl);                 \
                    mma16816h(O[2 * ng + 1], ph + 4 * kc, vh + 2);             \
                    mma16816h(O[2 * ng + 1], ph + 4 * kc, vl + 2);             \
                }                                                              \
            }                                                                  \
            float p00 = ex2(S[2 * kc][0] - mn0);                               \
            float p01 = ex2(S[2 * kc][1] - mn0);                               \
            float p02 = ex2(S[2 * kc][2] - mn1);                               \
            float p03 = ex2(S[2 * kc][3] - mn1);                               \
            float p10 = ex2(S[2 * kc + 1][0] - mn0);                           \
            float p11 = ex2(S[2 * kc + 1][1] - mn0);                           \
            float p12 = ex2(S[2 * kc + 1][2] - mn1);                           \
            float p13 = ex2(S[2 * kc + 1][3] - mn1);                           \
            ls0 += p00 + p01 + p10 + p11;                                      \
            ls1 += p02 + p03 + p12 + p13;                                      \
            pn[4 * kc + 0] = pack_h2(p00, p01);                                \
            pn[4 * kc + 1] = pack_h2(p02, p03);                                \
            pn[4 * kc + 2] = pack_h2(p10, p11);                                \
            pn[4 * kc + 3] = pack_h2(p12, p13);                                \
        }                                                                      \
        _Pragma("unroll")                                                      \
        for (int nt = 0; nt < 8; nt++) {                                       \
            O[nt][0] *= cr0; O[nt][1] *= cr0;                                  \
            O[nt][2] *= cr1; O[nt][3] *= cr1;                                  \
        }                                                                      \
        l0 = l0 * cr0 + ls0;                                                   \
        l1 = l1 * cr1 + ls1;                                                   \
        m0r = mn0; m1r = mn1;                                                  \
        _Pragma("unroll")                                                      \
        for (int i = 0; i < 16; i++) ph[i] = pn[i];                            \
    } while (0)

    // chunk 0 (no deferred PV yet)
    CP_WAIT(1);
    __syncthreads();
    ATTN_COMPUTE(0, 0);
    __syncthreads();
    attn_load(hoff, voff, 2 * 64, sb + 2 * STG_A, tid);
    CP_COMMIT();

    for (int s = 1; s < NCHUNK - 2; s++) {
        CP_WAIT(1);
        __syncthreads();
        ATTN_COMPUTE(s, 1);
        __syncthreads();
        attn_load(hoff, voff, (s + 2) * 64, sb + ((s + 2) & 3) * STG_A, tid);
        CP_COMMIT();
    }
    CP_WAIT(1); __syncthreads(); ATTN_COMPUTE(NCHUNK - 2, 1); __syncthreads();
    CP_WAIT(0); __syncthreads(); ATTN_COMPUTE(NCHUNK - 1, 1);

    // ---- tail: PV for the last chunk
    {
        const uint32_t bpv = sb + ((NCHUNK - 1) & 3) * STG_A;
        #pragma unroll
        for (int kc = 0; kc < 4; kc++) {
            #pragma unroll
            for (int ng = 0; ng < 4; ng++) {
                uint32_t vh[4], vl[4];
                uint32_t ad = bpv + 8192 + swzK(ng * 16 + rAdd, kc * 2 + cAdd3);
                ldmx4(vh, ad);
                ldmx4(vl, ad + 8192);
                mma16816h(O[2 * ng],     ph + 4 * kc, vh);
                mma16816h(O[2 * ng],     ph + 4 * kc, vl);
                mma16816h(O[2 * ng + 1], ph + 4 * kc, vh + 2);
                mma16816h(O[2 * ng + 1], ph + 4 * kc, vl + 2);
            }
        }
    }

    // ---- epilogue: normalize, split to fp16 hi/lo (proj A-operand), store
    l0 += __shfl_xor_sync(0xffffffffu, l0, 1);
    l0 += __shfl_xor_sync(0xffffffffu, l0, 2);
    l1 += __shfl_xor_sync(0xffffffffu, l1, 1);
    l1 += __shfl_xor_sync(0xffffffffu, l1, 2);
    const float i0 = 1.f / l0, i1 = 1.f / l1;
    const int g = lid >> 2, t4 = lid & 3;
    const int r0 = q0 + wq * 16 + g;
    const size_t o0 = ((size_t)b * N_ + r0) * C_ + h * HD_;
    const size_t o1 = o0 + (size_t)8 * C_;
    #pragma unroll
    for (int nt = 0; nt < 8; nt++) {
        const int col = nt * 8 + 2 * t4;
        uint32_t hi, lo;
        split2h(O[nt][0] * i0, O[nt][1] * i0, hi, lo);
        *(uint32_t*)&g_aohi[o0 + col] = hi;
        *(uint32_t*)&g_aolo[o0 + col] = lo;
        split2h(O[nt][2] * i1, O[nt][3] * i1, hi, lo);
        *(uint32_t*)&g_aohi[o1 + col] = hi;
        *(uint32_t*)&g_aolo[o1 + col] = lo;
    }
}

// ---------------------------------------------------------------------------
extern "C" void kernel_launch(void* const* d_in, const int* in_sizes, int n_in,
                              void* d_out, int out_size)
{
    const float* x      = (const float*)d_in[0];
    const float* qbias  = (const float*)d_in[1];
    const float* kbias  = (const float*)d_in[2];
    const float* vbias  = (const float*)d_in[3];
    const float* W_qkv  = (const float*)d_in[4];
    const float* b_qkv  = (const float*)d_in[5];
    const float* W_proj = (const float*)d_in[6];
    const float* b_proj = (const float*)d_in[7];
    float* out = (float*)d_out;

    cudaFuncSetAttribute(tc_gemm<0>,
        cudaFuncAttributeMaxDynamicSharedMemorySize, 3 * STG_G);
    cudaFuncSetAttribute(tc_gemm<1>,
        cudaFuncAttributeMaxDynamicSharedMemorySize, 3 * STG_G);
    cudaFuncSetAttribute(attn_kernel,
        cudaFuncAttributeMaxDynamicSharedMemorySize, SMEM_AT);

    __half *xhi, *xlo, *w1h, *w2h, *aohi, *aolo;
    cudaGetSymbolAddress((void**)&xhi,  g_xhi);
    cudaGetSymbolAddress((void**)&xlo,  g_xlo);
    cudaGetSymbolAddress((void**)&w1h,  g_w1h);
    cudaGetSymbolAddress((void**)&w2h,  g_w2h);
    cudaGetSymbolAddress((void**)&aohi, g_aohi);
    cudaGetSymbolAddress((void**)&aolo, g_aolo);

    const int ntot = NX4 + NW14 + NW24;
    conv_all<<<(ntot + 255) / 256, 256>>>(x, W_qkv, W_proj);

    tc_gemm<0><<<dim3(NC3 / 128, (B_ * N_) / 128), 256, 3 * STG_G>>>(
        xhi, xlo, w1h, b_qkv, qbias, kbias, vbias, nullptr);
    attn_kernel<<<dim3(N_ / 128, H_, B_), 256, SMEM_AT>>>();
    tc_gemm<1><<<dim3(C_ / 128, (B_ * N_) / 128), 256, 3 * STG_G>>>(
        aohi, aolo, w2h, b_proj, nullptr, nullptr, nullptr, out);
}

// round 15
// speedup vs baseline: 1.1974x; 1.1974x over previous
#include <cuda_runtime.h>
#include <cuda_bf16.h>
#include <cuda_fp16.h>
#include <cstdint>

// Problem constants
#define B_  4
#define N_  2048
#define C_  768
#define H_  12
#define HD_ 64
#define NC3 2304
// q pre-scale folded with log2(e) so attention can use raw ex2
#define QSCALE_ (0.125f * 1.44269504088896340736f)

#define QKV_SZ ((size_t)B_ * H_ * N_ * HD_)   // 6291456

// Static scratch — all tensor-core operands fp16.
// GEMM A-operands: hi/lo pairs; weights + Q + K: single fp16; V: hi/lo.
__device__ __half g_qh[QKV_SZ];                           // [B,H,N,HD], pre-scaled
__device__ __half g_kh[QKV_SZ];                           // [B,H,N,HD]
__device__ __half g_vhi[QKV_SZ], g_vlo[QKV_SZ];          // [B,H,HD,N] (transposed)
__device__ __half g_xhi[(size_t)B_ * N_ * C_], g_xlo[(size_t)B_ * N_ * C_];
__device__ __half g_w1h[(size_t)C_ * NC3];
__device__ __half g_w2h[(size_t)C_ * C_];
__device__ __half g_aohi[(size_t)B_ * N_ * C_], g_aolo[(size_t)B_ * N_ * C_];

// ---------------------------------------------------------------------------
// Helpers
// ---------------------------------------------------------------------------
__device__ __forceinline__ uint32_t smem_u32(const void* p) {
    uint32_t a;
    asm("{ .reg .u64 t; cvta.to.shared.u64 t, %1; cvt.u32.u64 %0, t; }"
        : "=r"(a) : "l"(p));
    return a;
}
__device__ __forceinline__ void ldmx4(uint32_t* r, uint32_t addr) {
    asm volatile("ldmatrix.sync.aligned.m8n8.x4.shared.b16 {%0,%1,%2,%3}, [%4];"
                 : "=r"(r[0]), "=r"(r[1]), "=r"(r[2]), "=r"(r[3]) : "r"(addr));
}
__device__ __forceinline__ void ldmx4t(uint32_t* r, uint32_t addr) {
    asm volatile("ldmatrix.sync.aligned.m8n8.x4.trans.shared.b16 {%0,%1,%2,%3}, [%4];"
                 : "=r"(r[0]), "=r"(r[1]), "=r"(r[2]), "=r"(r[3]) : "r"(addr));
}
__device__ __forceinline__ void mma16816h(float* c, const uint32_t* a,
                                          const uint32_t* b) {
    asm volatile(
        "mma.sync.aligned.m16n8k16.row.col.f32.f16.f16.f32 "
        "{%0,%1,%2,%3}, {%4,%5,%6,%7}, {%8,%9}, {%0,%1,%2,%3};"
        : "+f"(c[0]), "+f"(c[1]), "+f"(c[2]), "+f"(c[3])
        : "r"(a[0]), "r"(a[1]), "r"(a[2]), "r"(a[3]), "r"(b[0]), "r"(b[1]));
}
__device__ __forceinline__ void split2h(float x, float y, uint32_t& hi, uint32_t& lo) {
    __half2 h = __floats2half2_rn(x, y);
    float hx = __half2float(__low2half(h)), hy = __half2float(__high2half(h));
    __half2 l = __floats2half2_rn(x - hx, y - hy);
    hi = *(uint32_t*)&h;
    lo = *(uint32_t*)&l;
}
__device__ __forceinline__ uint32_t pack_h2(float x, float y) {
    __half2 h = __floats2half2_rn(x, y);
    return *(uint32_t*)&h;
}
__device__ __forceinline__ float ex2(float x) {
    float y;
    asm("ex2.approx.ftz.f32 %0, %1;" : "=f"(y) : "f"(x));
    return y;
}
__device__ __forceinline__ void cpa16(uint32_t dst, const void* src) {
    asm volatile("cp.async.cg.shared.global [%0], [%1], 16;" :: "r"(dst), "l"(src));
}
#define CP_COMMIT()  asm volatile("cp.async.commit_group;")
#define CP_WAIT(n)   asm volatile("cp.async.wait_group " #n ";")

// ---------------------------------------------------------------------------
// Kernel 0: fp32 -> fp16 conversions. x: hi+lo split; weights: single round.
// ---------------------------------------------------------------------------
#define NX4  ((B_ * N_ * C_) / 4)
#define NW14 ((C_ * NC3) / 4)
#define NW24 ((C_ * C_) / 4)

__global__ __launch_bounds__(256) void conv_all(
    const float* __restrict__ x, const float* __restrict__ w1,
    const float* __restrict__ w2)
{
    int i = blockIdx.x * 256 + threadIdx.x;
    if (i < NX4) {
        float4 v = ((const float4*)x)[i];
        uint32_t h0, l0, h1, l1;
        split2h(v.x, v.y, h0, l0);
        split2h(v.z, v.w, h1, l1);
        ((uint2*)g_xhi)[i] = make_uint2(h0, h1);
        ((uint2*)g_xlo)[i] = make_uint2(l0, l1);
    } else if (i < NX4 + NW14) {
        int j = i - NX4;
        float4 v = ((const float4*)w1)[j];
        ((uint2*)g_w1h)[j] = make_uint2(pack_h2(v.x, v.y), pack_h2(v.z, v.w));
    } else if (i < NX4 + NW14 + NW24) {
        int j = i - NX4 - NW14;
        float4 v = ((const float4*)w2)[j];
        ((uint2*)g_w2h)[j] = make_uint2(pack_h2(v.x, v.y), pack_h2(v.z, v.w));
    }
}

// ---------------------------------------------------------------------------
// GEMM: fp16 asymmetric 2-term HMMA (A = hi+lo, B rounded once).
// 128x128 CTA tile, 8 warps (2x4, warp tile 64x32), K-stage 64,
// 2-stage cp.async ring (2 x 48KB), two syncs per stage, 2 CTAs/SM.
// Stage layout (bytes): Ahi[0,16K) Alo[16K,32K) Bh[32K,48K)
// ---------------------------------------------------------------------------
#define STG_G  49152
#define NSTG   12            // 768 / 64

// A: 128 rows x 64 k fp16 (128B/row, 8 x 16B chunks), swizzle c ^= r&7
__device__ __forceinline__ uint32_t swzA(int r, int c) {
    return (uint32_t)(r * 128 + ((c ^ (r & 7)) << 4));
}
// B: 64 k-rows x 128 n fp16 (256B/row, 16 x 16B chunks), swizzle c ^= r&7
__device__ __forceinline__ uint32_t swzB(int r, int c) {
    return (uint32_t)(r * 256 + ((c ^ (r & 7)) << 4));
}

template <int LDB>
__device__ __forceinline__ void gemm_load_stage(
    const __half* __restrict__ Ahi, const __half* __restrict__ Alo,
    const __half* __restrict__ Bh,
    int m0, int n0, int s, uint32_t sbase, int tid)
{
    const int k0 = s * 64;
    #pragma unroll
    for (int j = 0; j < 4; j++) {
        int idx = tid + 256 * j;          // 0..1023
        int row = idx >> 3, c = idx & 7;
        size_t gi = (size_t)(m0 + row) * C_ + k0 + c * 8;
        uint32_t d = sbase + swzA(row, c);
        cpa16(d, Ahi + gi);
        cpa16(d + 16384, Alo + gi);
    }
    #pragma unroll
    for (int j = 0; j < 4; j++) {
        int idx = tid + 256 * j;
        int row = idx >> 4, c = idx & 15;
        size_t gi = (size_t)(k0 + row) * LDB + n0 + c * 8;
        cpa16(sbase + 32768 + swzB(row, c), Bh + gi);
    }
}

template <int MODE>
__global__ __launch_bounds__(256, 2) void tc_gemm(
    const __half* __restrict__ Ahi, const __half* __restrict__ Alo,
    const __half* __restrict__ Bh,
    const float* __restrict__ biasRow,
    const float* __restrict__ qb, const float* __restrict__ kb,
    const float* __restrict__ vb, float* __restrict__ outp)
{
    constexpr int LDB = (MODE == 0) ? NC3 : C_;
    extern __shared__ __align__(16) char smem[];
    const uint32_t sb = smem_u32(smem);
    const int tid = threadIdx.x, lid = tid & 31, wid = tid >> 5;
    const int wm = wid >> 2, wn = wid & 3;
    const int n0 = blockIdx.x * 128, m0 = blockIdx.y * 128;

    float c[4][4][4];
    #pragma unroll
    for (int i = 0; i < 4; i++)
        #pragma unroll
        for (int j = 0; j < 4; j++)
            #pragma unroll
            for (int k = 0; k < 4; k++) c[i][j][k] = 0.f;

    gemm_load_stage<LDB>(Ahi, Alo, Bh, m0, n0, 0, sb, tid);
    CP_COMMIT();
    gemm_load_stage<LDB>(Ahi, Alo, Bh, m0, n0, 1, sb + STG_G, tid);
    CP_COMMIT();

    const int arow = wm * 64 + (lid & 15);
    const int ac   = lid >> 4;          // A 16B-chunk sub-index (0/1)
    const int bkr  = lid & 15;
    const int bch  = lid >> 4;

#define GEMM_COMPUTE(SIDX)                                                     \
    do {                                                                       \
        const uint32_t base = sb + ((SIDX) & 1) * STG_G;                       \
        _Pragma("unroll")                                                      \
        for (int kk = 0; kk < 4; kk++) {                                       \
            uint32_t ah[4][4], al[4][4];                                       \
            _Pragma("unroll")                                                  \
            for (int mt = 0; mt < 4; mt++) {                                   \
                int r = arow + mt * 16;                                        \
                uint32_t ad = base + swzA(r, kk * 2 + ac);                     \
                ldmx4(ah[mt], ad);                                             \
                ldmx4(al[mt], ad + 16384);                                     \
            }                                                                  \
            uint32_t bh[2][4];                                                 \
            _Pragma("unroll")                                                  \
            for (int np = 0; np < 2; np++) {                                   \
                uint32_t ad = base + 32768                                     \
                    + swzB(kk * 16 + bkr, wn * 4 + np * 2 + bch);              \
                ldmx4t(bh[np], ad);                                            \
            }                                                                  \
            _Pragma("unroll")                                                  \
            for (int mt = 0; mt < 4; mt++)                                     \
                _Pragma("unroll")                                              \
                for (int nt = 0; nt < 4; nt++)                                 \
                    mma16816h(c[mt][nt], ah[mt], &bh[nt >> 1][(nt & 1) * 2]);  \
            _Pragma("unroll")                                                  \
            for (int mt = 0; mt < 4; mt++)                                     \
                _Pragma("unroll")                                              \
                for (int nt = 0; nt < 4; nt++)                                 \
                    mma16816h(c[mt][nt], al[mt], &bh[nt >> 1][(nt & 1) * 2]);  \
        }                                                                      \
    } while (0)

    for (int s = 0; s < NSTG - 2; s++) {
        CP_WAIT(1);
        __syncthreads();
        GEMM_COMPUTE(s);
        __syncthreads();
        gemm_load_stage<LDB>(Ahi, Alo, Bh, m0, n0, s + 2,
                             sb + ((s + 2) & 1) * STG_G, tid);
        CP_COMMIT();
    }
    CP_WAIT(1); __syncthreads(); GEMM_COMPUTE(NSTG - 2); __syncthreads();
    CP_WAIT(0); __syncthreads(); GEMM_COMPUTE(NSTG - 1);

    // Epilogue (direct from fragments)
    const int g = lid >> 2, t4 = lid & 3;
    if (MODE == 0) {
        const int s3 = n0 / C_;
        const int loc0 = n0 - s3 * C_;
        #pragma unroll
        for (int mt = 0; mt < 4; mt++) {
            #pragma unroll
            for (int nt = 0; nt < 4; nt++) {
                const int colT = wn * 32 + nt * 8 + 2 * t4;
                const int loc = loc0 + colT;
                const int hh = loc >> 6, dd = loc & 63;
                const float b0v = biasRow[n0 + colT];
                const float b1v = biasRow[n0 + colT + 1];
                #pragma unroll
                for (int hf = 0; hf < 2; hf++) {
                    const int m = m0 + wm * 64 + mt * 16 + g + hf * 8;
                    const int bb = m >> 11, nn = m & 2047;
                    const size_t bidx =
                        (((size_t)bb * H_ + hh) * N_ + nn) * HD_ + dd;
                    float v0 = c[mt][nt][2 * hf] + b0v;
                    float v1 = c[mt][nt][2 * hf + 1] + b1v;
                    if (s3 == 0) {
                        v0 = (v0 + qb[bidx]) * QSCALE_;
                        v1 = (v1 + qb[bidx + 1]) * QSCALE_;
                        *(uint32_t*)&g_qh[bidx] = pack_h2(v0, v1);
                    } else if (s3 == 1) {
                        v0 += kb[bidx];
                        v1 += kb[bidx + 1];
                        *(uint32_t*)&g_kh[bidx] = pack_h2(v0, v1);
                    } else {
                        v0 += vb[bidx];
                        v1 += vb[bidx + 1];
                        const size_t vix =
                            (((size_t)bb * H_ + hh) * HD_ + dd) * N_ + nn;
                        __half h0 = __float2half_rn(v0);
                        __half h1 = __float2half_rn(v1);
                        g_vhi[vix] = h0;
                        g_vlo[vix] = __float2half_rn(v0 - __half2float(h0));
                        g_vhi[vix + N_] = h1;
                        g_vlo[vix + N_] = __float2half_rn(v1 - __half2float(h1));
                    }
                }
            }
        }
    } else {
        #pragma unroll
        for (int mt = 0; mt < 4; mt++)
            #pragma unroll
            for (int nt = 0; nt < 4; nt++) {
                const int colT = wn * 32 + nt * 8 + 2 * t4;
                const float b0v = biasRow[n0 + colT];
                const float b1v = biasRow[n0 + colT + 1];
                #pragma unroll
                for (int hf = 0; hf < 2; hf++) {
                    const int m = m0 + wm * 64 + mt * 16 + g + hf * 8;
                    float2 r;
                    r.x = c[mt][nt][2 * hf] + b0v;
                    r.y = c[mt][nt][2 * hf + 1] + b1v;
                    *(float2*)&outp[(size_t)m * C_ + n0 + colT] = r;
                }
            }
    }
}

// ---------------------------------------------------------------------------
// Attention: fp16 HMMA flash attention (R12 structure, Q single fp16).
// 128 q-rows/CTA, 8 warps x 16 rows, 64-key chunks, XOR-swizzled smem,
// 2-stage cp.async ring, 2 CTAs/SM.
// S = q_fl16 · k_fl16 ; O += p_fl16 · (v_hi + v_lo).
// Stage layout (bytes): Kh[0,8K) Vh[8K,16K) Vl[16K,24K)
// ---------------------------------------------------------------------------
#define STG_A  24576
#define NCHUNK 32

__device__ __forceinline__ uint32_t swzK(int r, int c) {
    return (uint32_t)(r * 128 + ((c ^ (r & 7)) << 4));
}

__device__ __forceinline__ void attn_load(
    size_t hoff, size_t voff, int kt, uint32_t sbase, int tid)
{
    #pragma unroll
    for (int j = 0; j < 2; j++) {
        int idx = 2 * tid + j;            // 0..511
        int row = idx >> 3, ch = idx & 7;
        uint32_t d = sbase + swzK(row, ch);
        size_t ki = hoff + (size_t)(kt + row) * HD_ + ch * 8;
        cpa16(d, g_kh + ki);
        size_t vi = voff + (size_t)row * N_ + kt + ch * 8;
        cpa16(d + 8192,  g_vhi + vi);
        cpa16(d + 16384, g_vlo + vi);
    }
}

__global__ __launch_bounds__(256, 2) void attn_kernel()
{
    extern __shared__ __align__(16) char smem[];
    const uint32_t sb = smem_u32(smem);
    const int tid = threadIdx.x, lid = tid & 31, wq = tid >> 5;
    const int qt = blockIdx.x, h = blockIdx.y, b = blockIdx.z;
    const size_t hoff = (size_t)(b * H_ + h) * N_ * HD_;
    const size_t voff = (size_t)(b * H_ + h) * HD_ * N_;
    const int q0 = qt * 128;

    // ---- stage Q (2 x 8KB halves), then frags
    #pragma unroll
    for (int j = 0; j < 2; j++) {
        int cid = tid + 256 * j;          // 0..511
        int row = cid >> 2, ch2 = (cid & 3) * 2;   // 2 chunks per thread
        size_t ga = hoff + (size_t)(q0 + row) * HD_ + ch2 * 8;
        uint32_t d0 = swzK(row & 63, ch2) + ((row >> 6) << 13);
        uint32_t d1 = swzK(row & 63, ch2 + 1) + ((row >> 6) << 13);
        *(float4*)(smem + d0) = *(const float4*)&g_qh[ga];
        *(float4*)(smem + d1) = *(const float4*)&g_qh[ga + 8];
    }
    __syncthreads();
    uint32_t aqh[4][4];
    {
        int row = wq * 16 + (lid & 15);
        int ch0 = (lid >> 4);
        #pragma unroll
        for (int kk = 0; kk < 4; kk++) {
            uint32_t ad = sb + ((row >> 6) << 13) + swzK(row & 63, kk * 2 + ch0);
            ldmx4(aqh[kk], ad);
        }
    }
    __syncthreads();

    // ---- prologue: K/V chunks 0,1
    attn_load(hoff, voff, 0, sb, tid);
    CP_COMMIT();
    attn_load(hoff, voff, 64, sb + STG_A, tid);
    CP_COMMIT();

    float O[8][4];
    #pragma unroll
    for (int i = 0; i < 8; i++)
        #pragma unroll
        for (int j = 0; j < 4; j++) O[i][j] = 0.f;
    float m0r = -1e30f, m1r = -1e30f, l0 = 0.f, l1 = 0.f;

    const int grp = lid >> 3, l8 = lid & 7;
    const int rAdd = ((grp >> 1) << 3) + l8;
    const int cAdd3 = (grp & 1);

#define ATTN_COMPUTE(SIDX)                                                     \
    do {                                                                       \
        const uint32_t base = sb + ((SIDX) & 1) * STG_A;                       \
        float S[8][4];                                                         \
        _Pragma("unroll")                                                      \
        for (int i = 0; i < 8; i++)                                            \
            _Pragma("unroll")                                                  \
            for (int j = 0; j < 4; j++) S[i][j] = 0.f;                         \
        _Pragma("unroll")                                                      \
        for (int kk = 0; kk < 4; kk++) {                                       \
            _Pragma("unroll")                                                  \
            for (int ng = 0; ng < 4; ng++) {                                   \
                uint32_t kh[4];                                                \
                uint32_t ad = base + swzK(ng * 16 + rAdd, kk * 2 + cAdd3);     \
                ldmx4(kh, ad);                                                 \
                mma16816h(S[2 * ng],     aqh[kk], kh);                         \
                mma16816h(S[2 * ng + 1], aqh[kk], kh + 2);                     \
            }                                                                  \
        }                                                                      \
        float mx0 = S[0][0], mx1 = S[0][2];                                    \
        _Pragma("unroll")                                                      \
        for (int nt = 0; nt < 8; nt++) {                                       \
            mx0 = fmaxf(mx0, fmaxf(S[nt][0], S[nt][1]));                       \
            mx1 = fmaxf(mx1, fmaxf(S[nt][2], S[nt][3]));                       \
        }                                                                      \
        mx0 = fmaxf(mx0, __shfl_xor_sync(0xffffffffu, mx0, 1));                \
        mx0 = fmaxf(mx0, __shfl_xor_sync(0xffffffffu, mx0, 2));                \
        mx1 = fmaxf(mx1, __shfl_xor_sync(0xffffffffu, mx1, 1));                \
        mx1 = fmaxf(mx1, __shfl_xor_sync(0xffffffffu, mx1, 2));                \
        const float mn0 = fmaxf(m0r, mx0), mn1 = fmaxf(m1r, mx1);              \
        const float cr0 = ex2(m0r - mn0), cr1 = ex2(m1r - mn1);                \
        l0 *= cr0; l1 *= cr1;                                                  \
        _Pragma("unroll")                                                      \
        for (int nt = 0; nt < 8; nt++) {                                       \
            O[nt][0] *= cr0; O[nt][1] *= cr0;                                  \
            O[nt][2] *= cr1; O[nt][3] *= cr1;                                  \
        }                                                                      \
        m0r = mn0; m1r = mn1;                                                  \
        _Pragma("unroll")                                                      \
        for (int kc = 0; kc < 4; kc++) {                                       \
            float p00 = ex2(S[2 * kc][0] - mn0);                               \
            float p01 = ex2(S[2 * kc][1] - mn0);                               \
            float p02 = ex2(S[2 * kc][2] - mn1);                               \
            float p03 = ex2(S[2 * kc][3] - mn1);                               \
            float p10 = ex2(S[2 * kc + 1][0] - mn0);                           \
            float p11 = ex2(S[2 * kc + 1][1] - mn0);                           \
            float p12 = ex2(S[2 * kc + 1][2] - mn1);                           \
            float p13 = ex2(S[2 * kc + 1][3] - mn1);                           \
            l0 += p00 + p01 + p10 + p11;                                       \
            l1 += p02 + p03 + p12 + p13;                                       \
            uint32_t ph[4];                                                    \
            ph[0] = pack_h2(p00, p01);                                         \
            ph[1] = pack_h2(p02, p03);                                         \
            ph[2] = pack_h2(p10, p11);                                         \
            ph[3] = pack_h2(p12, p13);                                         \
            _Pragma("unroll")                                                  \
            for (int ng = 0; ng < 4; ng++) {                                   \
                uint32_t vh[4], vl[4];                                         \
                uint32_t ad = base + 8192                                      \
                    + swzK(ng * 16 + rAdd, kc * 2 + cAdd3);                    \
                ldmx4(vh, ad);                                                 \
                ldmx4(vl, ad + 8192);                                          \
                mma16816h(O[2 * ng],     ph, vh);                              \
                mma16816h(O[2 * ng],     ph, vl);                              \
                mma16816h(O[2 * ng + 1], ph, vh + 2);                          \
                mma16816h(O[2 * ng + 1], ph, vl + 2);                          \
            }                                                                  \
        }                                                                      \
    } while (0)

    for (int s = 0; s < NCHUNK - 2; s++) {
        CP_WAIT(1);
        __syncthreads();
        ATTN_COMPUTE(s);
        __syncthreads();
        attn_load(hoff, voff, (s + 2) * 64, sb + ((s + 2) & 1) * STG_A, tid);
        CP_COMMIT();
    }
    CP_WAIT(1); __syncthreads(); ATTN_COMPUTE(NCHUNK - 2); __syncthreads();
    CP_WAIT(0); __syncthreads(); ATTN_COMPUTE(NCHUNK - 1);

    // ---- epilogue: normalize, split to fp16 hi/lo (proj A-operand), store
    l0 += __shfl_xor_sync(0xffffffffu, l0, 1);
    l0 += __shfl_xor_sync(0xffffffffu, l0, 2);
    l1 += __shfl_xor_sync(0xffffffffu, l1, 1);
    l1 += __shfl_xor_sync(0xffffffffu, l1, 2);
    const float i0 = 1.f / l0, i1 = 1.f / l1;
    const int g = lid >> 2, t4 = lid & 3;
    const int r0 = q0 + wq * 16 + g;
    const size_t o0 = ((size_t)b * N_ + r0) * C_ + h * HD_;
    const size_t o1 = o0 + (size_t)8 * C_;
    #pragma unroll
    for (int nt = 0; nt < 8; nt++) {
        const int col = nt * 8 + 2 * t4;
        uint32_t hi, lo;
        split2h(O[nt][0] * i0, O[nt][1] * i0, hi, lo);
        *(uint32_t*)&g_aohi[o0 + col] = hi;
        *(uint32_t*)&g_aolo[o0 + col] = lo;
        split2h(O[nt][2] * i1, O[nt][3] * i1, hi, lo);
        *(uint32_t*)&g_aohi[o1 + col] = hi;
        *(uint32_t*)&g_aolo[o1 + col] = lo;
    }
}

// ---------------------------------------------------------------------------
extern "C" void kernel_launch(void* const* d_in, const int* in_sizes, int n_in,
                              void* d_out, int out_size)
{
    const float* x      = (const float*)d_in[0];
    const float* qbias  = (const float*)d_in[1];
    const float* kbias  = (const float*)d_in[2];
    const float* vbias  = (const float*)d_in[3];
    const float* W_qkv  = (const float*)d_in[4];
    const float* b_qkv  = (const float*)d_in[5];
    const float* W_proj = (const float*)d_in[6];
    const float* b_proj = (const float*)d_in[7];
    float* out = (float*)d_out;

    cudaFuncSetAttribute(tc_gemm<0>,
        cudaFuncAttributeMaxDynamicSharedMemorySize, 2 * STG_G);
    cudaFuncSetAttribute(tc_gemm<1>,
        cudaFuncAttributeMaxDynamicSharedMemorySize, 2 * STG_G);
    cudaFuncSetAttribute(attn_kernel,
        cudaFuncAttributeMaxDynamicSharedMemorySize, 2 * STG_A);

    __half *xhi, *xlo, *w1h, *w2h, *aohi, *aolo;
    cudaGetSymbolAddress((void**)&xhi,  g_xhi);
    cudaGetSymbolAddress((void**)&xlo,  g_xlo);
    cudaGetSymbolAddress((void**)&w1h,  g_w1h);
    cudaGetSymbolAddress((void**)&w2h,  g_w2h);
    cudaGetSymbolAddress((void**)&aohi, g_aohi);
    cudaGetSymbolAddress((void**)&aolo, g_aolo);

    const int ntot = NX4 + NW14 + NW24;
    conv_all<<<(ntot + 255) / 256, 256>>>(x, W_qkv, W_proj);

    tc_gemm<0><<<dim3(NC3 / 128, (B_ * N_) / 128), 256, 2 * STG_G>>>(
        xhi, xlo, w1h, b_qkv, qbias, kbias, vbias, nullptr);
    attn_kernel<<<dim3(N_ / 128, H_, B_), 256, 2 * STG_A>>>();
    tc_gemm<1><<<dim3(C_ / 128, (B_ * N_) / 128), 256, 2 * STG_G>>>(
        aohi, aolo, w2h, b_proj, nullptr, nullptr, nullptr, out);
}

// round 16
// speedup vs baseline: 1.3992x; 1.1686x over previous
#include <cuda_runtime.h>
#include <cuda_bf16.h>
#include <cuda_fp16.h>
#include <cstdint>

// Problem constants
#define B_  4
#define N_  2048
#define C_  768
#define H_  12
#define HD_ 64
#define NC3 2304
// q pre-scale folded with log2(e) so attention can use raw ex2
#define QSCALE_ (0.125f * 1.44269504088896340736f)

#define QKV_SZ ((size_t)B_ * H_ * N_ * HD_)   // 6291456

// Static scratch — all tensor-core operands fp16.
// GEMM A-operands: hi/lo pairs; weights + Q + K + V: single fp16.
__device__ __half g_qh[QKV_SZ];                           // [B,H,N,HD], pre-scaled
__device__ __half g_kh[QKV_SZ];                           // [B,H,N,HD]
__device__ __half g_vh[QKV_SZ];                           // [B,H,HD,N] (transposed)
__device__ __half g_xhi[(size_t)B_ * N_ * C_], g_xlo[(size_t)B_ * N_ * C_];
__device__ __half g_w1h[(size_t)C_ * NC3];
__device__ __half g_w2h[(size_t)C_ * C_];
__device__ __half g_aohi[(size_t)B_ * N_ * C_], g_aolo[(size_t)B_ * N_ * C_];

// ---------------------------------------------------------------------------
// Helpers
// ---------------------------------------------------------------------------
__device__ __forceinline__ uint32_t smem_u32(const void* p) {
    uint32_t a;
    asm("{ .reg .u64 t; cvta.to.shared.u64 t, %1; cvt.u32.u64 %0, t; }"
        : "=r"(a) : "l"(p));
    return a;
}
__device__ __forceinline__ void ldmx4(uint32_t* r, uint32_t addr) {
    asm volatile("ldmatrix.sync.aligned.m8n8.x4.shared.b16 {%0,%1,%2,%3}, [%4];"
                 : "=r"(r[0]), "=r"(r[1]), "=r"(r[2]), "=r"(r[3]) : "r"(addr));
}
__device__ __forceinline__ void ldmx4t(uint32_t* r, uint32_t addr) {
    asm volatile("ldmatrix.sync.aligned.m8n8.x4.trans.shared.b16 {%0,%1,%2,%3}, [%4];"
                 : "=r"(r[0]), "=r"(r[1]), "=r"(r[2]), "=r"(r[3]) : "r"(addr));
}
__device__ __forceinline__ void mma16816h(float* c, const uint32_t* a,
                                          const uint32_t* b) {
    asm volatile(
        "mma.sync.aligned.m16n8k16.row.col.f32.f16.f16.f32 "
        "{%0,%1,%2,%3}, {%4,%5,%6,%7}, {%8,%9}, {%0,%1,%2,%3};"
        : "+f"(c[0]), "+f"(c[1]), "+f"(c[2]), "+f"(c[3])
        : "r"(a[0]), "r"(a[1]), "r"(a[2]), "r"(a[3]), "r"(b[0]), "r"(b[1]));
}
__device__ __forceinline__ void split2h(float x, float y, uint32_t& hi, uint32_t& lo) {
    __half2 h = __floats2half2_rn(x, y);
    float hx = __half2float(__low2half(h)), hy = __half2float(__high2half(h));
    __half2 l = __floats2half2_rn(x - hx, y - hy);
    hi = *(uint32_t*)&h;
    lo = *(uint32_t*)&l;
}
__device__ __forceinline__ uint32_t pack_h2(float x, float y) {
    __half2 h = __floats2half2_rn(x, y);
    return *(uint32_t*)&h;
}
__device__ __forceinline__ float ex2(float x) {
    float y;
    asm("ex2.approx.ftz.f32 %0, %1;" : "=f"(y) : "f"(x));
    return y;
}
__device__ __forceinline__ void cpa16(uint32_t dst, const void* src) {
    asm volatile("cp.async.cg.shared.global [%0], [%1], 16;" :: "r"(dst), "l"(src));
}
#define CP_COMMIT()  asm volatile("cp.async.commit_group;")
#define CP_WAIT(n)   asm volatile("cp.async.wait_group " #n ";")

// ---------------------------------------------------------------------------
// Kernel 0: fp32 -> fp16 conversions. x: hi+lo split; weights: single round.
// ---------------------------------------------------------------------------
#define NX4  ((B_ * N_ * C_) / 4)
#define NW14 ((C_ * NC3) / 4)
#define NW24 ((C_ * C_) / 4)

__global__ __launch_bounds__(256) void conv_all(
    const float* __restrict__ x, const float* __restrict__ w1,
    const float* __restrict__ w2)
{
    int i = blockIdx.x * 256 + threadIdx.x;
    if (i < NX4) {
        float4 v = ((const float4*)x)[i];
        uint32_t h0, l0, h1, l1;
        split2h(v.x, v.y, h0, l0);
        split2h(v.z, v.w, h1, l1);
        ((uint2*)g_xhi)[i] = make_uint2(h0, h1);
        ((uint2*)g_xlo)[i] = make_uint2(l0, l1);
    } else if (i < NX4 + NW14) {
        int j = i - NX4;
        float4 v = ((const float4*)w1)[j];
        ((uint2*)g_w1h)[j] = make_uint2(pack_h2(v.x, v.y), pack_h2(v.z, v.w));
    } else if (i < NX4 + NW14 + NW24) {
        int j = i - NX4 - NW14;
        float4 v = ((const float4*)w2)[j];
        ((uint2*)g_w2h)[j] = make_uint2(pack_h2(v.x, v.y), pack_h2(v.z, v.w));
    }
}

// ---------------------------------------------------------------------------
// GEMM: fp16 asymmetric 2-term HMMA (A = hi+lo, B rounded once).
// 128x128 CTA tile, 8 warps (2x4, warp tile 64x32), K-stage 64,
// 2-stage cp.async ring (2 x 48KB), two syncs per stage, 2 CTAs/SM.
// (unchanged from round 15 — proven)
// Stage layout (bytes): Ahi[0,16K) Alo[16K,32K) Bh[32K,48K)
// ---------------------------------------------------------------------------
#define STG_G  49152
#define NSTG   12            // 768 / 64

__device__ __forceinline__ uint32_t swzA(int r, int c) {
    return (uint32_t)(r * 128 + ((c ^ (r & 7)) << 4));
}
__device__ __forceinline__ uint32_t swzB(int r, int c) {
    return (uint32_t)(r * 256 + ((c ^ (r & 7)) << 4));
}

template <int LDB>
__device__ __forceinline__ void gemm_load_stage(
    const __half* __restrict__ Ahi, const __half* __restrict__ Alo,
    const __half* __restrict__ Bh,
    int m0, int n0, int s, uint32_t sbase, int tid)
{
    const int k0 = s * 64;
    #pragma unroll
    for (int j = 0; j < 4; j++) {
        int idx = tid + 256 * j;          // 0..1023
        int row = idx >> 3, c = idx & 7;
        size_t gi = (size_t)(m0 + row) * C_ + k0 + c * 8;
        uint32_t d = sbase + swzA(row, c);
        cpa16(d, Ahi + gi);
        cpa16(d + 16384, Alo + gi);
    }
    #pragma unroll
    for (int j = 0; j < 4; j++) {
        int idx = tid + 256 * j;
        int row = idx >> 4, c = idx & 15;
        size_t gi = (size_t)(k0 + row) * LDB + n0 + c * 8;
        cpa16(sbase + 32768 + swzB(row, c), Bh + gi);
    }
}

template <int MODE>
__global__ __launch_bounds__(256, 2) void tc_gemm(
    const __half* __restrict__ Ahi, const __half* __restrict__ Alo,
    const __half* __restrict__ Bh,
    const float* __restrict__ biasRow,
    const float* __restrict__ qb, const float* __restrict__ kb,
    const float* __restrict__ vb, float* __restrict__ outp)
{
    constexpr int LDB = (MODE == 0) ? NC3 : C_;
    extern __shared__ __align__(16) char smem[];
    const uint32_t sb = smem_u32(smem);
    const int tid = threadIdx.x, lid = tid & 31, wid = tid >> 5;
    const int wm = wid >> 2, wn = wid & 3;
    const int n0 = blockIdx.x * 128, m0 = blockIdx.y * 128;

    float c[4][4][4];
    #pragma unroll
    for (int i = 0; i < 4; i++)
        #pragma unroll
        for (int j = 0; j < 4; j++)
            #pragma unroll
            for (int k = 0; k < 4; k++) c[i][j][k] = 0.f;

    gemm_load_stage<LDB>(Ahi, Alo, Bh, m0, n0, 0, sb, tid);
    CP_COMMIT();
    gemm_load_stage<LDB>(Ahi, Alo, Bh, m0, n0, 1, sb + STG_G, tid);
    CP_COMMIT();

    const int arow = wm * 64 + (lid & 15);
    const int ac   = lid >> 4;
    const int bkr  = lid & 15;
    const int bch  = lid >> 4;

#define GEMM_COMPUTE(SIDX)                                                     \
    do {                                                                       \
        const uint32_t base = sb + ((SIDX) & 1) * STG_G;                       \
        _Pragma("unroll")                                                      \
        for (int kk = 0; kk < 4; kk++) {                                       \
            uint32_t ah[4][4], al[4][4];                                       \
            _Pragma("unroll")                                                  \
            for (int mt = 0; mt < 4; mt++) {                                   \
                int r = arow + mt * 16;                                        \
                uint32_t ad = base + swzA(r, kk * 2 + ac);                     \
                ldmx4(ah[mt], ad);                                             \
                ldmx4(al[mt], ad + 16384);                                     \
            }                                                                  \
            uint32_t bh[2][4];                                                 \
            _Pragma("unroll")                                                  \
            for (int np = 0; np < 2; np++) {                                   \
                uint32_t ad = base + 32768                                     \
                    + swzB(kk * 16 + bkr, wn * 4 + np * 2 + bch);              \
                ldmx4t(bh[np], ad);                                            \
            }                                                                  \
            _Pragma("unroll")                                                  \
            for (int mt = 0; mt < 4; mt++)                                     \
                _Pragma("unroll")                                              \
                for (int nt = 0; nt < 4; nt++)                                 \
                    mma16816h(c[mt][nt], ah[mt], &bh[nt >> 1][(nt & 1) * 2]);  \
            _Pragma("unroll")                                                  \
            for (int mt = 0; mt < 4; mt++)                                     \
                _Pragma("unroll")                                              \
                for (int nt = 0; nt < 4; nt++)                                 \
                    mma16816h(c[mt][nt], al[mt], &bh[nt >> 1][(nt & 1) * 2]);  \
        }                                                                      \
    } while (0)

    for (int s = 0; s < NSTG - 2; s++) {
        CP_WAIT(1);
        __syncthreads();
        GEMM_COMPUTE(s);
        __syncthreads();
        gemm_load_stage<LDB>(Ahi, Alo, Bh, m0, n0, s + 2,
                             sb + ((s + 2) & 1) * STG_G, tid);
        CP_COMMIT();
    }
    CP_WAIT(1); __syncthreads(); GEMM_COMPUTE(NSTG - 2); __syncthreads();
    CP_WAIT(0); __syncthreads(); GEMM_COMPUTE(NSTG - 1);

    // Epilogue (direct from fragments)
    const int g = lid >> 2, t4 = lid & 3;
    if (MODE == 0) {
        const int s3 = n0 / C_;
        const int loc0 = n0 - s3 * C_;
        #pragma unroll
        for (int mt = 0; mt < 4; mt++) {
            #pragma unroll
            for (int nt = 0; nt < 4; nt++) {
                const int colT = wn * 32 + nt * 8 + 2 * t4;
                const int loc = loc0 + colT;
                const int hh = loc >> 6, dd = loc & 63;
                const float b0v = biasRow[n0 + colT];
                const float b1v = biasRow[n0 + colT + 1];
                #pragma unroll
                for (int hf = 0; hf < 2; hf++) {
                    const int m = m0 + wm * 64 + mt * 16 + g + hf * 8;
                    const int bb = m >> 11, nn = m & 2047;
                    const size_t bidx =
                        (((size_t)bb * H_ + hh) * N_ + nn) * HD_ + dd;
                    float v0 = c[mt][nt][2 * hf] + b0v;
                    float v1 = c[mt][nt][2 * hf + 1] + b1v;
                    if (s3 == 0) {
                        v0 = (v0 + qb[bidx]) * QSCALE_;
                        v1 = (v1 + qb[bidx + 1]) * QSCALE_;
                        *(uint32_t*)&g_qh[bidx] = pack_h2(v0, v1);
                    } else if (s3 == 1) {
                        v0 += kb[bidx];
                        v1 += kb[bidx + 1];
                        *(uint32_t*)&g_kh[bidx] = pack_h2(v0, v1);
                    } else {
                        v0 += vb[bidx];
                        v1 += vb[bidx + 1];
                        const size_t vix =
                            (((size_t)bb * H_ + hh) * HD_ + dd) * N_ + nn;
                        g_vh[vix] = __float2half_rn(v0);
                        g_vh[vix + N_] = __float2half_rn(v1);
                    }
                }
            }
        }
    } else {
        #pragma unroll
        for (int mt = 0; mt < 4; mt++)
            #pragma unroll
            for (int nt = 0; nt < 4; nt++) {
                const int colT = wn * 32 + nt * 8 + 2 * t4;
                const float b0v = biasRow[n0 + colT];
                const float b1v = biasRow[n0 + colT + 1];
                #pragma unroll
                for (int hf = 0; hf < 2; hf++) {
                    const int m = m0 + wm * 64 + mt * 16 + g + hf * 8;
                    float2 r;
                    r.x = c[mt][nt][2 * hf] + b0v;
                    r.y = c[mt][nt][2 * hf + 1] + b1v;
                    *(float2*)&outp[(size_t)m * C_ + n0 + colT] = r;
                }
            }
    }
}

// ---------------------------------------------------------------------------
// Attention: fp16 HMMA flash attention (R15 structure, V single fp16 now).
// 128 q-rows/CTA, 8 warps x 16 rows, 64-key chunks, XOR-swizzled smem,
// 2-stage cp.async ring, 2 CTAs/SM.
// S = q_fl16 · k_fl16 ; O += p_fl16 · v_fl16.
// Stage layout (bytes): Kh[0,8K) Vh[8K,16K)
// ---------------------------------------------------------------------------
#define STG_A  16384
#define NCHUNK 32

__device__ __forceinline__ uint32_t swzK(int r, int c) {
    return (uint32_t)(r * 128 + ((c ^ (r & 7)) << 4));
}

__device__ __forceinline__ void attn_load(
    size_t hoff, size_t voff, int kt, uint32_t sbase, int tid)
{
    #pragma unroll
    for (int j = 0; j < 2; j++) {
        int idx = 2 * tid + j;            // 0..511
        int row = idx >> 3, ch = idx & 7;
        uint32_t d = sbase + swzK(row, ch);
        size_t ki = hoff + (size_t)(kt + row) * HD_ + ch * 8;
        cpa16(d, g_kh + ki);
        size_t vi = voff + (size_t)row * N_ + kt + ch * 8;
        cpa16(d + 8192, g_vh + vi);
    }
}

__global__ __launch_bounds__(256, 2) void attn_kernel()
{
    extern __shared__ __align__(16) char smem[];
    const uint32_t sb = smem_u32(smem);
    const int tid = threadIdx.x, lid = tid & 31, wq = tid >> 5;
    const int qt = blockIdx.x, h = blockIdx.y, b = blockIdx.z;
    const size_t hoff = (size_t)(b * H_ + h) * N_ * HD_;
    const size_t voff = (size_t)(b * H_ + h) * HD_ * N_;
    const int q0 = qt * 128;

    // ---- stage Q (2 x 8KB halves), then frags
    #pragma unroll
    for (int j = 0; j < 2; j++) {
        int cid = tid + 256 * j;          // 0..511
        int row = cid >> 2, ch2 = (cid & 3) * 2;   // 2 chunks per thread
        size_t ga = hoff + (size_t)(q0 + row) * HD_ + ch2 * 8;
        uint32_t d0 = swzK(row & 63, ch2) + ((row >> 6) << 13);
        uint32_t d1 = swzK(row & 63, ch2 + 1) + ((row >> 6) << 13);
        *(float4*)(smem + d0) = *(const float4*)&g_qh[ga];
        *(float4*)(smem + d1) = *(const float4*)&g_qh[ga + 8];
    }
    __syncthreads();
    uint32_t aqh[4][4];
    {
        int row = wq * 16 + (lid & 15);
        int ch0 = (lid >> 4);
        #pragma unroll
        for (int kk = 0; kk < 4; kk++) {
            uint32_t ad = sb + ((row >> 6) << 13) + swzK(row & 63, kk * 2 + ch0);
            ldmx4(aqh[kk], ad);
        }
    }
    __syncthreads();

    // ---- prologue: K/V chunks 0,1
    attn_load(hoff, voff, 0, sb, tid);
    CP_COMMIT();
    attn_load(hoff, voff, 64, sb + STG_A, tid);
    CP_COMMIT();

    float O[8][4];
    #pragma unroll
    for (int i = 0; i < 8; i++)
        #pragma unroll
        for (int j = 0; j < 4; j++) O[i][j] = 0.f;
    float m0r = -1e30f, m1r = -1e30f, l0 = 0.f, l1 = 0.f;

    const int grp = lid >> 3, l8 = lid & 7;
    const int rAdd = ((grp >> 1) << 3) + l8;
    const int cAdd3 = (grp & 1);

#define ATTN_COMPUTE(SIDX)                                                     \
    do {                                                                       \
        const uint32_t base = sb + ((SIDX) & 1) * STG_A;                       \
        float S[8][4];                                                         \
        _Pragma("unroll")                                                      \
        for (int i = 0; i < 8; i++)                                            \
            _Pragma("unroll")                                                  \
            for (int j = 0; j < 4; j++) S[i][j] = 0.f;                         \
        _Pragma("unroll")                                                      \
        for (int kk = 0; kk < 4; kk++) {                                       \
            _Pragma("unroll")                                                  \
            for (int ng = 0; ng < 4; ng++) {                                   \
                uint32_t kh[4];                                                \
                uint32_t ad = base + swzK(ng * 16 + rAdd, kk * 2 + cAdd3);     \
                ldmx4(kh, ad);                                                 \
                mma16816h(S[2 * ng],     aqh[kk], kh);                         \
                mma16816h(S[2 * ng + 1], aqh[kk], kh + 2);                     \
            }                                                                  \
        }                                                                      \
        float mx0 = S[0][0], mx1 = S[0][2];                                    \
        _Pragma("unroll")                                                      \
        for (int nt = 0; nt < 8; nt++) {                                       \
            mx0 = fmaxf(mx0, fmaxf(S[nt][0], S[nt][1]));                       \
            mx1 = fmaxf(mx1, fmaxf(S[nt][2], S[nt][3]));                       \
        }                                                                      \
        mx0 = fmaxf(mx0, __shfl_xor_sync(0xffffffffu, mx0, 1));                \
        mx0 = fmaxf(mx0, __shfl_xor_sync(0xffffffffu, mx0, 2));                \
        mx1 = fmaxf(mx1, __shfl_xor_sync(0xffffffffu, mx1, 1));                \
        mx1 = fmaxf(mx1, __shfl_xor_sync(0xffffffffu, mx1, 2));                \
        const float mn0 = fmaxf(m0r, mx0), mn1 = fmaxf(m1r, mx1);              \
        const float cr0 = ex2(m0r - mn0), cr1 = ex2(m1r - mn1);                \
        l0 *= cr0; l1 *= cr1;                                                  \
        _Pragma("unroll")                                                      \
        for (int nt = 0; nt < 8; nt++) {                                       \
            O[nt][0] *= cr0; O[nt][1] *= cr0;                                  \
            O[nt][2] *= cr1; O[nt][3] *= cr1;                                  \
        }                                                                      \
        m0r = mn0; m1r = mn1;                                                  \
        _Pragma("unroll")                                                      \
        for (int kc = 0; kc < 4; kc++) {                                       \
            float p00 = ex2(S[2 * kc][0] - mn0);                               \
            float p01 = ex2(S[2 * kc][1] - mn0);                               \
            float p02 = ex2(S[2 * kc][2] - mn1);                               \
            float p03 = ex2(S[2 * kc][3] - mn1);                               \
            float p10 = ex2(S[2 * kc + 1][0] - mn0);                           \
            float p11 = ex2(S[2 * kc + 1][1] - mn0);                           \
            float p12 = ex2(S[2 * kc + 1][2] - mn1);                           \
            float p13 = ex2(S[2 * kc + 1][3] - mn1);                           \
            l0 += p00 + p01 + p10 + p11;                                       \
            l1 += p02 + p03 + p12 + p13;                                       \
            uint32_t ph[4];                                                    \
            ph[0] = pack_h2(p00, p01);                                         \
            ph[1] = pack_h2(p02, p03);                                         \
            ph[2] = pack_h2(p10, p11);                                         \
            ph[3] = pack_h2(p12, p13);                                         \
            _Pragma("unroll")                                                  \
            for (int ng = 0; ng < 4; ng++) {                                   \
                uint32_t vh[4];                                                \
                uint32_t ad = base + 8192                                      \
                    + swzK(ng * 16 + rAdd, kc * 2 + cAdd3);                    \
                ldmx4(vh, ad);                                                 \
                mma16816h(O[2 * ng],     ph, vh);                              \
                mma16816h(O[2 * ng + 1], ph, vh + 2);                          \
            }                                                                  \
        }                                                                      \
    } while (0)

    for (int s = 0; s < NCHUNK - 2; s++) {
        CP_WAIT(1);
        __syncthreads();
        ATTN_COMPUTE(s);
        __syncthreads();
        attn_load(hoff, voff, (s + 2) * 64, sb + ((s + 2) & 1) * STG_A, tid);
        CP_COMMIT();
    }
    CP_WAIT(1); __syncthreads(); ATTN_COMPUTE(NCHUNK - 2); __syncthreads();
    CP_WAIT(0); __syncthreads(); ATTN_COMPUTE(NCHUNK - 1);

    // ---- epilogue: normalize, split to fp16 hi/lo (proj A-operand), store
    l0 += __shfl_xor_sync(0xffffffffu, l0, 1);
    l0 += __shfl_xor_sync(0xffffffffu, l0, 2);
    l1 += __shfl_xor_sync(0xffffffffu, l1, 1);
    l1 += __shfl_xor_sync(0xffffffffu, l1, 2);
    const float i0 = 1.f / l0, i1 = 1.f / l1;
    const int g = lid >> 2, t4 = lid & 3;
    const int r0 = q0 + wq * 16 + g;
    const size_t o0 = ((size_t)b * N_ + r0) * C_ + h * HD_;
    const size_t o1 = o0 + (size_t)8 * C_;
    #pragma unroll
    for (int nt = 0; nt < 8; nt++) {
        const int col = nt * 8 + 2 * t4;
        uint32_t hi, lo;
        split2h(O[nt][0] * i0, O[nt][1] * i0, hi, lo);
        *(uint32_t*)&g_aohi[o0 + col] = hi;
        *(uint32_t*)&g_aolo[o0 + col] = lo;
        split2h(O[nt][2] * i1, O[nt][3] * i1, hi, lo);
        *(uint32_t*)&g_aohi[o1 + col] = hi;
        *(uint32_t*)&g_aolo[o1 + col] = lo;
    }
}

// ---------------------------------------------------------------------------
extern "C" void kernel_launch(void* const* d_in, const int* in_sizes, int n_in,
                              void* d_out, int out_size)
{
    const float* x      = (const float*)d_in[0];
    const float* qbias  = (const float*)d_in[1];
    const float* kbias  = (const float*)d_in[2];
    const float* vbias  = (const float*)d_in[3];
    const float* W_qkv  = (const float*)d_in[4];
    const float* b_qkv  = (const float*)d_in[5];
    const float* W_proj = (const float*)d_in[6];
    const float* b_proj = (const float*)d_in[7];
    float* out = (float*)d_out;

    cudaFuncSetAttribute(tc_gemm<0>,
        cudaFuncAttributeMaxDynamicSharedMemorySize, 2 * STG_G);
    cudaFuncSetAttribute(tc_gemm<1>,
        cudaFuncAttributeMaxDynamicSharedMemorySize, 2 * STG_G);
    cudaFuncSetAttribute(attn_kernel,
        cudaFuncAttributeMaxDynamicSharedMemorySize, 2 * STG_A);

    __half *xhi, *xlo, *w1h, *w2h, *aohi, *aolo;
    cudaGetSymbolAddress((void**)&xhi,  g_xhi);
    cudaGetSymbolAddress((void**)&xlo,  g_xlo);
    cudaGetSymbolAddress((void**)&w1h,  g_w1h);
    cudaGetSymbolAddress((void**)&w2h,  g_w2h);
    cudaGetSymbolAddress((void**)&aohi, g_aohi);
    cudaGetSymbolAddress((void**)&aolo, g_aolo);

    const int ntot = NX4 + NW14 + NW24;
    conv_all<<<(ntot + 255) / 256, 256>>>(x, W_qkv, W_proj);

    tc_gemm<0><<<dim3(NC3 / 128, (B_ * N_) / 128), 256, 2 * STG_G>>>(
        xhi, xlo, w1h, b_qkv, qbias, kbias, vbias, nullptr);
    attn_kernel<<<dim3(N_ / 128, H_, B_), 256, 2 * STG_A>>>();
    tc_gemm<1><<<dim3(C_ / 128, (B_ * N_) / 128), 256, 2 * STG_G>>>(
        aohi, aolo, w2h, b_proj, nullptr, nullptr, nullptr, out);
}

// round 17
// speedup vs baseline: 1.4005x; 1.0009x over previous
#include <cuda_runtime.h>
#include <cuda_bf16.h>
#include <cuda_fp16.h>
#include <cstdint>

// Problem constants
#define B_  4
#define N_  2048
#define C_  768
#define H_  12
#define HD_ 64
#define NC3 2304
// q pre-scale folded with log2(e) so attention can use raw ex2
#define QSCALE_ (0.125f * 1.44269504088896340736f)

#define QKV_SZ ((size_t)B_ * H_ * N_ * HD_)   // 6291456

// Static scratch — all tensor-core operands fp16.
// GEMM A-operands: hi/lo pairs; weights + Q + K + V: single fp16.
__device__ __half g_qh[QKV_SZ];                           // [B,H,N,HD], pre-scaled
__device__ __half g_kh[QKV_SZ];                           // [B,H,N,HD]
__device__ __half g_vh[QKV_SZ];                           // [B,H,HD,N] (transposed)
__device__ __half g_xhi[(size_t)B_ * N_ * C_], g_xlo[(size_t)B_ * N_ * C_];
__device__ __half g_w1h[(size_t)C_ * NC3];
__device__ __half g_w2h[(size_t)C_ * C_];
__device__ __half g_aohi[(size_t)B_ * N_ * C_], g_aolo[(size_t)B_ * N_ * C_];

// ---------------------------------------------------------------------------
// Helpers
// ---------------------------------------------------------------------------
__device__ __forceinline__ uint32_t smem_u32(const void* p) {
    uint32_t a;
    asm("{ .reg .u64 t; cvta.to.shared.u64 t, %1; cvt.u32.u64 %0, t; }"
        : "=r"(a) : "l"(p));
    return a;
}
__device__ __forceinline__ void ldmx4(uint32_t* r, uint32_t addr) {
    asm volatile("ldmatrix.sync.aligned.m8n8.x4.shared.b16 {%0,%1,%2,%3}, [%4];"
                 : "=r"(r[0]), "=r"(r[1]), "=r"(r[2]), "=r"(r[3]) : "r"(addr));
}
__device__ __forceinline__ void ldmx4t(uint32_t* r, uint32_t addr) {
    asm volatile("ldmatrix.sync.aligned.m8n8.x4.trans.shared.b16 {%0,%1,%2,%3}, [%4];"
                 : "=r"(r[0]), "=r"(r[1]), "=r"(r[2]), "=r"(r[3]) : "r"(addr));
}
__device__ __forceinline__ void mma16816h(float* c, const uint32_t* a,
                                          const uint32_t* b) {
    asm volatile(
        "mma.sync.aligned.m16n8k16.row.col.f32.f16.f16.f32 "
        "{%0,%1,%2,%3}, {%4,%5,%6,%7}, {%8,%9}, {%0,%1,%2,%3};"
        : "+f"(c[0]), "+f"(c[1]), "+f"(c[2]), "+f"(c[3])
        : "r"(a[0]), "r"(a[1]), "r"(a[2]), "r"(a[3]), "r"(b[0]), "r"(b[1]));
}
__device__ __forceinline__ void split2h(float x, float y, uint32_t& hi, uint32_t& lo) {
    __half2 h = __floats2half2_rn(x, y);
    float hx = __half2float(__low2half(h)), hy = __half2float(__high2half(h));
    __half2 l = __floats2half2_rn(x - hx, y - hy);
    hi = *(uint32_t*)&h;
    lo = *(uint32_t*)&l;
}
__device__ __forceinline__ uint32_t pack_h2(float x, float y) {
    __half2 h = __floats2half2_rn(x, y);
    return *(uint32_t*)&h;
}
__device__ __forceinline__ float ex2(float x) {
    float y;
    asm("ex2.approx.ftz.f32 %0, %1;" : "=f"(y) : "f"(x));
    return y;
}
__device__ __forceinline__ void cpa16(uint32_t dst, const void* src) {
    asm volatile("cp.async.cg.shared.global [%0], [%1], 16;" :: "r"(dst), "l"(src));
}
#define CP_COMMIT()  asm volatile("cp.async.commit_group;")
#define CP_WAIT(n)   asm volatile("cp.async.wait_group " #n ";")

// ---------------------------------------------------------------------------
// Kernel 0: fp32 -> fp16 conversions. x: hi+lo split; weights: single round.
// ---------------------------------------------------------------------------
#define NX4  ((B_ * N_ * C_) / 4)
#define NW14 ((C_ * NC3) / 4)
#define NW24 ((C_ * C_) / 4)

__global__ __launch_bounds__(256) void conv_all(
    const float* __restrict__ x, const float* __restrict__ w1,
    const float* __restrict__ w2)
{
    int i = blockIdx.x * 256 + threadIdx.x;
    if (i < NX4) {
        float4 v = ((const float4*)x)[i];
        uint32_t h0, l0, h1, l1;
        split2h(v.x, v.y, h0, l0);
        split2h(v.z, v.w, h1, l1);
        ((uint2*)g_xhi)[i] = make_uint2(h0, h1);
        ((uint2*)g_xlo)[i] = make_uint2(l0, l1);
    } else if (i < NX4 + NW14) {
        int j = i - NX4;
        float4 v = ((const float4*)w1)[j];
        ((uint2*)g_w1h)[j] = make_uint2(pack_h2(v.x, v.y), pack_h2(v.z, v.w));
    } else if (i < NX4 + NW14 + NW24) {
        int j = i - NX4 - NW14;
        float4 v = ((const float4*)w2)[j];
        ((uint2*)g_w2h)[j] = make_uint2(pack_h2(v.x, v.y), pack_h2(v.z, v.w));
    }
}

// ---------------------------------------------------------------------------
// GEMM: fp16 asymmetric 2-term HMMA (A = hi+lo, B rounded once).
// 128x128 CTA tile, 8 warps (2x4, warp tile 64x32), K-stage 64,
// 2-stage cp.async ring (2 x 48KB), two syncs per stage, 2 CTAs/SM.
// (unchanged from round 15 — proven)
// Stage layout (bytes): Ahi[0,16K) Alo[16K,32K) Bh[32K,48K)
// ---------------------------------------------------------------------------
#define STG_G  49152
#define NSTG   12            // 768 / 64

__device__ __forceinline__ uint32_t swzA(int r, int c) {
    return (uint32_t)(r * 128 + ((c ^ (r & 7)) << 4));
}
__device__ __forceinline__ uint32_t swzB(int r, int c) {
    return (uint32_t)(r * 256 + ((c ^ (r & 7)) << 4));
}

template <int LDB>
__device__ __forceinline__ void gemm_load_stage(
    const __half* __restrict__ Ahi, const __half* __restrict__ Alo,
    const __half* __restrict__ Bh,
    int m0, int n0, int s, uint32_t sbase, int tid)
{
    const int k0 = s * 64;
    #pragma unroll
    for (int j = 0; j < 4; j++) {
        int idx = tid + 256 * j;          // 0..1023
        int row = idx >> 3, c = idx & 7;
        size_t gi = (size_t)(m0 + row) * C_ + k0 + c * 8;
        uint32_t d = sbase + swzA(row, c);
        cpa16(d, Ahi + gi);
        cpa16(d + 16384, Alo + gi);
    }
    #pragma unroll
    for (int j = 0; j < 4; j++) {
        int idx = tid + 256 * j;
        int row = idx >> 4, c = idx & 15;
        size_t gi = (size_t)(k0 + row) * LDB + n0 + c * 8;
        cpa16(sbase + 32768 + swzB(row, c), Bh + gi);
    }
}

template <int MODE>
__global__ __launch_bounds__(256, 2) void tc_gemm(
    const __half* __restrict__ Ahi, const __half* __restrict__ Alo,
    const __half* __restrict__ Bh,
    const float* __restrict__ biasRow,
    const float* __restrict__ qb, const float* __restrict__ kb,
    const float* __restrict__ vb, float* __restrict__ outp)
{
    constexpr int LDB = (MODE == 0) ? NC3 : C_;
    extern __shared__ __align__(16) char smem[];
    const uint32_t sb = smem_u32(smem);
    const int tid = threadIdx.x, lid = tid & 31, wid = tid >> 5;
    const int wm = wid >> 2, wn = wid & 3;
    const int n0 = blockIdx.x * 128, m0 = blockIdx.y * 128;

    float c[4][4][4];
    #pragma unroll
    for (int i = 0; i < 4; i++)
        #pragma unroll
        for (int j = 0; j < 4; j++)
            #pragma unroll
            for (int k = 0; k < 4; k++) c[i][j][k] = 0.f;

    gemm_load_stage<LDB>(Ahi, Alo, Bh, m0, n0, 0, sb, tid);
    CP_COMMIT();
    gemm_load_stage<LDB>(Ahi, Alo, Bh, m0, n0, 1, sb + STG_G, tid);
    CP_COMMIT();

    const int arow = wm * 64 + (lid & 15);
    const int ac   = lid >> 4;
    const int bkr  = lid & 15;
    const int bch  = lid >> 4;

#define GEMM_COMPUTE(SIDX)                                                     \
    do {                                                                       \
        const uint32_t base = sb + ((SIDX) & 1) * STG_G;                       \
        _Pragma("unroll")                                                      \
        for (int kk = 0; kk < 4; kk++) {                                       \
            uint32_t ah[4][4], al[4][4];                                       \
            _Pragma("unroll")                                                  \
            for (int mt = 0; mt < 4; mt++) {                                   \
                int r = arow + mt * 16;                                        \
                uint32_t ad = base + swzA(r, kk * 2 + ac);                     \
                ldmx4(ah[mt], ad);                                             \
                ldmx4(al[mt], ad + 16384);                                     \
            }                                                                  \
            uint32_t bh[2][4];                                                 \
            _Pragma("unroll")                                                  \
            for (int np = 0; np < 2; np++) {                                   \
                uint32_t ad = base + 32768                                     \
                    + swzB(kk * 16 + bkr, wn * 4 + np * 2 + bch);              \
                ldmx4t(bh[np], ad);                                            \
            }                                                                  \
            _Pragma("unroll")                                                  \
            for (int mt = 0; mt < 4; mt++)                                     \
                _Pragma("unroll")                                              \
                for (int nt = 0; nt < 4; nt++)                                 \
                    mma16816h(c[mt][nt], ah[mt], &bh[nt >> 1][(nt & 1) * 2]);  \
            _Pragma("unroll")                                                  \
            for (int mt = 0; mt < 4; mt++)                                     \
                _Pragma("unroll")                                              \
                for (int nt = 0; nt < 4; nt++)                                 \
                    mma16816h(c[mt][nt], al[mt], &bh[nt >> 1][(nt & 1) * 2]);  \
        }                                                                      \
    } while (0)

    for (int s = 0; s < NSTG - 2; s++) {
        CP_WAIT(1);
        __syncthreads();
        GEMM_COMPUTE(s);
        __syncthreads();
        gemm_load_stage<LDB>(Ahi, Alo, Bh, m0, n0, s + 2,
                             sb + ((s + 2) & 1) * STG_G, tid);
        CP_COMMIT();
    }
    CP_WAIT(1); __syncthreads(); GEMM_COMPUTE(NSTG - 2); __syncthreads();
    CP_WAIT(0); __syncthreads(); GEMM_COMPUTE(NSTG - 1);

    // Epilogue (direct from fragments)
    const int g = lid >> 2, t4 = lid & 3;
    if (MODE == 0) {
        const int s3 = n0 / C_;
        const int loc0 = n0 - s3 * C_;
        #pragma unroll
        for (int mt = 0; mt < 4; mt++) {
            #pragma unroll
            for (int nt = 0; nt < 4; nt++) {
                const int colT = wn * 32 + nt * 8 + 2 * t4;
                const int loc = loc0 + colT;
                const int hh = loc >> 6, dd = loc & 63;
                const float b0v = biasRow[n0 + colT];
                const float b1v = biasRow[n0 + colT + 1];
                #pragma unroll
                for (int hf = 0; hf < 2; hf++) {
                    const int m = m0 + wm * 64 + mt * 16 + g + hf * 8;
                    const int bb = m >> 11, nn = m & 2047;
                    const size_t bidx =
                        (((size_t)bb * H_ + hh) * N_ + nn) * HD_ + dd;
                    float v0 = c[mt][nt][2 * hf] + b0v;
                    float v1 = c[mt][nt][2 * hf + 1] + b1v;
                    if (s3 == 0) {
                        v0 = (v0 + qb[bidx]) * QSCALE_;
                        v1 = (v1 + qb[bidx + 1]) * QSCALE_;
                        *(uint32_t*)&g_qh[bidx] = pack_h2(v0, v1);
                    } else if (s3 == 1) {
                        v0 += kb[bidx];
                        v1 += kb[bidx + 1];
                        *(uint32_t*)&g_kh[bidx] = pack_h2(v0, v1);
                    } else {
                        v0 += vb[bidx];
                        v1 += vb[bidx + 1];
                        const size_t vix =
                            (((size_t)bb * H_ + hh) * HD_ + dd) * N_ + nn;
                        g_vh[vix] = __float2half_rn(v0);
                        g_vh[vix + N_] = __float2half_rn(v1);
                    }
                }
            }
        }
    } else {
        #pragma unroll
        for (int mt = 0; mt < 4; mt++)
            #pragma unroll
            for (int nt = 0; nt < 4; nt++) {
                const int colT = wn * 32 + nt * 8 + 2 * t4;
                const float b0v = biasRow[n0 + colT];
                const float b1v = biasRow[n0 + colT + 1];
                #pragma unroll
                for (int hf = 0; hf < 2; hf++) {
                    const int m = m0 + wm * 64 + mt * 16 + g + hf * 8;
                    float2 r;
                    r.x = c[mt][nt][2 * hf] + b0v;
                    r.y = c[mt][nt][2 * hf + 1] + b1v;
                    *(float2*)&outp[(size_t)m * C_ + n0 + colT] = r;
                }
            }
    }
}

// ---------------------------------------------------------------------------
// Attention: fp16 HMMA flash attention (R15 structure, V single fp16 now).
// 128 q-rows/CTA, 8 warps x 16 rows, 64-key chunks, XOR-swizzled smem,
// 2-stage cp.async ring, 2 CTAs/SM.
// S = q_fl16 · k_fl16 ; O += p_fl16 · v_fl16.
// Stage layout (bytes): Kh[0,8K) Vh[8K,16K)
// ---------------------------------------------------------------------------
#define STG_A  16384
#define NCHUNK 32

__device__ __forceinline__ uint32_t swzK(int r, int c) {
    return (uint32_t)(r * 128 + ((c ^ (r & 7)) << 4));
}

__device__ __forceinline__ void attn_load(
    size_t hoff, size_t voff, int kt, uint32_t sbase, int tid)
{
    #pragma unroll
    for (int j = 0; j < 2; j++) {
        int idx = 2 * tid + j;            // 0..511
        int row = idx >> 3, ch = idx & 7;
        uint32_t d = sbase + swzK(row, ch);
        size_t ki = hoff + (size_t)(kt + row) * HD_ + ch * 8;
        cpa16(d, g_kh + ki);
        size_t vi = voff + (size_t)row * N_ + kt + ch * 8;
        cpa16(d + 8192, g_vh + vi);
    }
}

__global__ __launch_bounds__(256, 2) void attn_kernel()
{
    extern __shared__ __align__(16) char smem[];
    const uint32_t sb = smem_u32(smem);
    const int tid = threadIdx.x, lid = tid & 31, wq = tid >> 5;
    const int qt = blockIdx.x, h = blockIdx.y, b = blockIdx.z;
    const size_t hoff = (size_t)(b * H_ + h) * N_ * HD_;
    const size_t voff = (size_t)(b * H_ + h) * HD_ * N_;
    const int q0 = qt * 128;

    // ---- stage Q (2 x 8KB halves), then frags
    #pragma unroll
    for (int j = 0; j < 2; j++) {
        int cid = tid + 256 * j;          // 0..511
        int row = cid >> 2, ch2 = (cid & 3) * 2;   // 2 chunks per thread
        size_t ga = hoff + (size_t)(q0 + row) * HD_ + ch2 * 8;
        uint32_t d0 = swzK(row & 63, ch2) + ((row >> 6) << 13);
        uint32_t d1 = swzK(row & 63, ch2 + 1) + ((row >> 6) << 13);
        *(float4*)(smem + d0) = *(const float4*)&g_qh[ga];
        *(float4*)(smem + d1) = *(const float4*)&g_qh[ga + 8];
    }
    __syncthreads();
    uint32_t aqh[4][4];
    {
        int row = wq * 16 + (lid & 15);
        int ch0 = (lid >> 4);
        #pragma unroll
        for (int kk = 0; kk < 4; kk++) {
            uint32_t ad = sb + ((row >> 6) << 13) + swzK(row & 63, kk * 2 + ch0);
            ldmx4(aqh[kk], ad);
        }
    }
    __syncthreads();

    // ---- prologue: K/V chunks 0,1
    attn_load(hoff, voff, 0, sb, tid);
    CP_COMMIT();
    attn_load(hoff, voff, 64, sb + STG_A, tid);
    CP_COMMIT();

    float O[8][4];
    #pragma unroll
    for (int i = 0; i < 8; i++)
        #pragma unroll
        for (int j = 0; j < 4; j++) O[i][j] = 0.f;
    float m0r = -1e30f, m1r = -1e30f, l0 = 0.f, l1 = 0.f;

    const int grp = lid >> 3, l8 = lid & 7;
    const int rAdd = ((grp >> 1) << 3) + l8;
    const int cAdd3 = (grp & 1);

#define ATTN_COMPUTE(SIDX)                                                     \
    do {                                                                       \
        const uint32_t base = sb + ((SIDX) & 1) * STG_A;                       \
        float S[8][4];                                                         \
        _Pragma("unroll")                                                      \
        for (int i = 0; i < 8; i++)                                            \
            _Pragma("unroll")                                                  \
            for (int j = 0; j < 4; j++) S[i][j] = 0.f;                         \
        _Pragma("unroll")                                                      \
        for (int kk = 0; kk < 4; kk++) {                                       \
            _Pragma("unroll")                                                  \
            for (int ng = 0; ng < 4; ng++) {                                   \
                uint32_t kh[4];                                                \
                uint32_t ad = base + swzK(ng * 16 + rAdd, kk * 2 + cAdd3);     \
                ldmx4(kh, ad);                                                 \
                mma16816h(S[2 * ng],     aqh[kk], kh);                         \
                mma16816h(S[2 * ng + 1], aqh[kk], kh + 2);                     \
            }                                                                  \
        }                                                                      \
        float mx0 = S[0][0], mx1 = S[0][2];                                    \
        _Pragma("unroll")                                                      \
        for (int nt = 0; nt < 8; nt++) {                                       \
            mx0 = fmaxf(mx0, fmaxf(S[nt][0], S[nt][1]));                       \
            mx1 = fmaxf(mx1, fmaxf(S[nt][2], S[nt][3]));                       \
        }                                                                      \
        mx0 = fmaxf(mx0, __shfl_xor_sync(0xffffffffu, mx0, 1));                \
        mx0 = fmaxf(mx0, __shfl_xor_sync(0xffffffffu, mx0, 2));                \
        mx1 = fmaxf(mx1, __shfl_xor_sync(0xffffffffu, mx1, 1));                \
        mx1 = fmaxf(mx1, __shfl_xor_sync(0xffffffffu, mx1, 2));                \
        const float mn0 = fmaxf(m0r, mx0), mn1 = fmaxf(m1r, mx1);              \
        const float cr0 = ex2(m0r - mn0), cr1 = ex2(m1r - mn1);                \
        l0 *= cr0; l1 *= cr1;                                                  \
        _Pragma("unroll")                                                      \
        for (int nt = 0; nt < 8; nt++) {                                       \
            O[nt][0] *= cr0; O[nt][1] *= cr0;                                  \
            O[nt][2] *= cr1; O[nt][3] *= cr1;                                  \
        }                                                                      \
        m0r = mn0; m1r = mn1;                                                  \
        _Pragma("unroll")                                                      \
        for (int kc = 0; kc < 4; kc++) {                                       \
            float p00 = ex2(S[2 * kc][0] - mn0);                               \
            float p01 = ex2(S[2 * kc][1] - mn0);                               \
            float p02 = ex2(S[2 * kc][2] - mn1);                               \
            float p03 = ex2(S[2 * kc][3] - mn1);                               \
            float p10 = ex2(S[2 * kc + 1][0] - mn0);                           \
            float p11 = ex2(S[2 * kc + 1][1] - mn0);                           \
            float p12 = ex2(S[2 * kc + 1][2] - mn1);                           \
            float p13 = ex2(S[2 * kc + 1][3] - mn1);                           \
            l0 += p00 + p01 + p10 + p11;                                       \
            l1 += p02 + p03 + p12 + p13;                                       \
            uint32_t ph[4];                                                    \
            ph[0] = pack_h2(p00, p01);                                         \
            ph[1] = pack_h2(p02, p03);                                         \
            ph[2] = pack_h2(p10, p11);                                         \
            ph[3] = pack_h2(p12, p13);                                         \
            _Pragma("unroll")                                                  \
            for (int ng = 0; ng < 4; ng++) {                                   \
                uint32_t vh[4];                                                \
                uint32_t ad = base + 8192                                      \
                    + swzK(ng * 16 + rAdd, kc * 2 + cAdd3);                    \
                ldmx4(vh, ad);                                                 \
                mma16816h(O[2 * ng],     ph, vh);                              \
                mma16816h(O[2 * ng + 1], ph, vh + 2);                          \
            }                                                                  \
        }                                                                      \
    } while (0)

    for (int s = 0; s < NCHUNK - 2; s++) {
        CP_WAIT(1);
        __syncthreads();
        ATTN_COMPUTE(s);
        __syncthreads();
        attn_load(hoff, voff, (s + 2) * 64, sb + ((s + 2) & 1) * STG_A, tid);
        CP_COMMIT();
    }
    CP_WAIT(1); __syncthreads(); ATTN_COMPUTE(NCHUNK - 2); __syncthreads();
    CP_WAIT(0); __syncthreads(); ATTN_COMPUTE(NCHUNK - 1);

    // ---- epilogue: normalize, split to fp16 hi/lo (proj A-operand), store
    l0 += __shfl_xor_sync(0xffffffffu, l0, 1);
    l0 += __shfl_xor_sync(0xffffffffu, l0, 2);
    l1 += __shfl_xor_sync(0xffffffffu, l1, 1);
    l1 += __shfl_xor_sync(0xffffffffu, l1, 2);
    const float i0 = 1.f / l0, i1 = 1.f / l1;
    const int g = lid >> 2, t4 = lid & 3;
    const int r0 = q0 + wq * 16 + g;
    const size_t o0 = ((size_t)b * N_ + r0) * C_ + h * HD_;
    const size_t o1 = o0 + (size_t)8 * C_;
    #pragma unroll
    for (int nt = 0; nt < 8; nt++) {
        const int col = nt * 8 + 2 * t4;
        uint32_t hi, lo;
        split2h(O[nt][0] * i0, O[nt][1] * i0, hi, lo);
        *(uint32_t*)&g_aohi[o0 + col] = hi;
        *(uint32_t*)&g_aolo[o0 + col] = lo;
        split2h(O[nt][2] * i1, O[nt][3] * i1, hi, lo);
        *(uint32_t*)&g_aohi[o1 + col] = hi;
        *(uint32_t*)&g_aolo[o1 + col] = lo;
    }
}

// ---------------------------------------------------------------------------
extern "C" void kernel_launch(void* const* d_in, const int* in_sizes, int n_in,
                              void* d_out, int out_size)
{
    const float* x      = (const float*)d_in[0];
    const float* qbias  = (const float*)d_in[1];
    const float* kbias  = (const float*)d_in[2];
    const float* vbias  = (const float*)d_in[3];
    const float* W_qkv  = (const float*)d_in[4];
    const float* b_qkv  = (const float*)d_in[5];
    const float* W_proj = (const float*)d_in[6];
    const float* b_proj = (const float*)d_in[7];
    float* out = (float*)d_out;

    cudaFuncSetAttribute(tc_gemm<0>,
        cudaFuncAttributeMaxDynamicSharedMemorySize, 2 * STG_G);
    cudaFuncSetAttribute(tc_gemm<1>,
        cudaFuncAttributeMaxDynamicSharedMemorySize, 2 * STG_G);
    cudaFuncSetAttribute(attn_kernel,
        cudaFuncAttributeMaxDynamicSharedMemorySize, 2 * STG_A);

    __half *xhi, *xlo, *w1h, *w2h, *aohi, *aolo;
    cudaGetSymbolAddress((void**)&xhi,  g_xhi);
    cudaGetSymbolAddress((void**)&xlo,  g_xlo);
    cudaGetSymbolAddress((void**)&w1h,  g_w1h);
    cudaGetSymbolAddress((void**)&w2h,  g_w2h);
    cudaGetSymbolAddress((void**)&aohi, g_aohi);
    cudaGetSymbolAddress((void**)&aolo, g_aolo);

    const int ntot = NX4 + NW14 + NW24;
    conv_all<<<(ntot + 255) / 256, 256>>>(x, W_qkv, W_proj);

    tc_gemm<0><<<dim3(NC3 / 128, (B_ * N_) / 128), 256, 2 * STG_G>>>(
        xhi, xlo, w1h, b_qkv, qbias, kbias, vbias, nullptr);
    attn_kernel<<<dim3(N_ / 128, H_, B_), 256, 2 * STG_A>>>();
    tc_gemm<1><<<dim3(C_ / 128, (B_ * N_) / 128), 256, 2 * STG_G>>>(
        aohi, aolo, w2h, b_proj, nullptr, nullptr, nullptr, out);
}